// round 1
// baseline (speedup 1.0000x reference)
#include <cuda_runtime.h>
#include <math.h>

#define Bsz 64
#define T 512
#define D 512
#define H 512
#define NG 2048  // 4*H
#define MTOT (Bsz*T)  // 32768

// Scratch: hoisted input projections (time-major [T][B][4H]) + recurrent state.
__device__ float g_ZF[(size_t)T * Bsz * NG];   // 268 MB
__device__ float g_ZB[(size_t)T * Bsz * NG];   // 268 MB
__device__ float g_h[2][2][Bsz * H];           // [pingpong][dir][B*H]
__device__ float g_c[2][Bsz * H];              // [dir][B*H]

__global__ void init_kernel() {
    int i = blockIdx.x * blockDim.x + threadIdx.x;
    if (i < Bsz * H) {
        g_h[0][0][i] = 0.f; g_h[0][1][i] = 0.f;
        g_h[1][0][i] = 0.f; g_h[1][1][i] = 0.f;
        g_c[0][i] = 0.f;    g_c[1][i] = 0.f;
    }
}

// ---------------------------------------------------------------------------
// Phase 1: Z = x @ W[:D] + b for BOTH directions in one GEMM.
// A: [M=32768, K=512] where m = t*B + b (time-major output rows)
// B: [K=512, N=4096]  (n < 2048 -> W_fw rows 0..511 ; else W_bw)
// C: g_ZF / g_ZB, [T*B, 2048] each.
// 128x128 tile, BK=16, 8x8 microtile, 256 threads.
// ---------------------------------------------------------------------------
__global__ void __launch_bounds__(256) gemm_x_kernel(
    const float* __restrict__ x,
    const float* __restrict__ Wfw, const float* __restrict__ bfw,
    const float* __restrict__ Wbw, const float* __restrict__ bbw)
{
    __shared__ float As[16][132];   // padded: stride 132 floats (16B-aligned rows)
    __shared__ float Bs[16][128];

    const int tid = threadIdx.x;
    const int bm = blockIdx.y * 128;
    const int bn = blockIdx.x * 128;          // 0..4095
    const int dir = (bn >= 2048) ? 1 : 0;
    const float* __restrict__ W = dir ? Wbw : Wfw;
    const int n0 = dir ? (bn - 2048) : bn;

    const int tr = tid >> 4;   // 0..15
    const int tc = tid & 15;   // 0..15

    float acc[8][8];
#pragma unroll
    for (int i = 0; i < 8; i++)
#pragma unroll
        for (int j = 0; j < 8; j++) acc[i][j] = 0.f;

    for (int kk = 0; kk < D; kk += 16) {
        // Load A tile (128 rows x 16 k), transposed into As[k][m]
#pragma unroll
        for (int ld = 0; ld < 2; ld++) {
            int id = tid + ld * 256;             // 0..511
            int ml = id >> 2;                    // 0..127
            int k4 = (id & 3) * 4;
            int m = bm + ml;
            int b_ = m & (Bsz - 1);
            int t_ = m >> 6;
            const float4 v = *(const float4*)(x + ((size_t)b_ * T + t_) * D + kk + k4);
            As[k4 + 0][ml] = v.x; As[k4 + 1][ml] = v.y;
            As[k4 + 2][ml] = v.z; As[k4 + 3][ml] = v.w;
        }
        // Load B tile (16 k x 128 n)
#pragma unroll
        for (int ld = 0; ld < 2; ld++) {
            int id = tid + ld * 256;             // 0..511
            int kl = id >> 5;                    // 0..15
            int n4 = (id & 31) * 4;
            const float4 v = *(const float4*)(W + (size_t)(kk + kl) * NG + n0 + n4);
            *(float4*)&Bs[kl][n4] = v;
        }
        __syncthreads();
#pragma unroll
        for (int k = 0; k < 16; k++) {
            float a[8], bb[8];
            *(float4*)&a[0] = *(const float4*)&As[k][tr * 8];
            *(float4*)&a[4] = *(const float4*)&As[k][tr * 8 + 4];
            *(float4*)&bb[0] = *(const float4*)&Bs[k][tc * 8];
            *(float4*)&bb[4] = *(const float4*)&Bs[k][tc * 8 + 4];
#pragma unroll
            for (int i = 0; i < 8; i++)
#pragma unroll
                for (int j = 0; j < 8; j++) acc[i][j] += a[i] * bb[j];
        }
        __syncthreads();
    }

    float* __restrict__ Z = dir ? g_ZB : g_ZF;
    const float* __restrict__ bias = dir ? bbw : bfw;
#pragma unroll
    for (int i = 0; i < 8; i++) {
        int m = bm + tr * 8 + i;
#pragma unroll
        for (int j = 0; j < 8; j += 4) {
            int n = n0 + tc * 8 + j;
            float4 v;
            v.x = acc[i][j + 0] + bias[n + 0];
            v.y = acc[i][j + 1] + bias[n + 1];
            v.z = acc[i][j + 2] + bias[n + 2];
            v.w = acc[i][j + 3] + bias[n + 3];
            *(float4*)(Z + (size_t)m * NG + n) = v;
        }
    }
}

// ---------------------------------------------------------------------------
// Phase 2: one kernel per timestep, fw + bw fused.
// Per block: 64 batch rows x 8 h-cols x 4 gates of the recurrent GEMM
// (A = h_prev [64,512], B = W[D:, gate*H + hcol]), then fused gate math,
// c/h update, and output write. 128 blocks (64 per dir), 256 threads.
// ---------------------------------------------------------------------------
__global__ void __launch_bounds__(256) step_kernel(
    int s,
    const float* __restrict__ Wfw, const float* __restrict__ Wbw,
    float* __restrict__ out)
{
    const int dir = blockIdx.x >> 6;            // 0: fw, 1: bw
    const int hTile = (blockIdx.x & 63) * 8;    // 8 h-cols per block
    const float* __restrict__ W = dir ? Wbw : Wfw;
    const int t = dir ? (T - 1 - s) : s;
    const float* __restrict__ Z = dir ? g_ZB : g_ZF;
    const float* __restrict__ hprev = g_h[s & 1][dir];
    float* __restrict__ hnext = g_h[(s & 1) ^ 1][dir];
    float* __restrict__ cst = g_c[dir];

    __shared__ float As[32][65];   // padded for transpose-store conflicts
    __shared__ float Bs[32][32];   // cols: gate*8 + hcl

    const int tid = threadIdx.x;
    const int rg = tid >> 3;     // 0..31 -> rows rg*2, rg*2+1
    const int hcl = tid & 7;     // 0..7

    float acc[2][4];
#pragma unroll
    for (int i = 0; i < 2; i++)
#pragma unroll
        for (int g = 0; g < 4; g++) acc[i][g] = 0.f;

    for (int kk = 0; kk < H; kk += 32) {
        // A: h_prev tile 64 rows x 32 k, transposed -> As[k][row]
#pragma unroll
        for (int ld = 0; ld < 2; ld++) {
            int id = tid + ld * 256;          // 0..511
            int ml = id >> 3;                 // 0..63
            int k4 = (id & 7) * 4;
            float4 v = *(const float4*)(hprev + ml * H + kk + k4);
            As[k4 + 0][ml] = v.x; As[k4 + 1][ml] = v.y;
            As[k4 + 2][ml] = v.z; As[k4 + 3][ml] = v.w;
        }
        // B: 32 k x (4 gates x 8 hcols)
        {
            int kl = tid >> 3;                 // 0..31
            int rem = tid & 7;
            int g = rem >> 1;
            int h4 = (rem & 1) * 4;
            float4 v = *(const float4*)(W + (size_t)(D + kk + kl) * NG + g * H + hTile + h4);
            *(float4*)&Bs[kl][g * 8 + h4] = v;
        }
        __syncthreads();
#pragma unroll
        for (int k = 0; k < 32; k++) {
            float a0 = As[k][rg * 2], a1 = As[k][rg * 2 + 1];
            float b0 = Bs[k][hcl], b1 = Bs[k][8 + hcl];
            float b2 = Bs[k][16 + hcl], b3 = Bs[k][24 + hcl];
            acc[0][0] += a0 * b0; acc[0][1] += a0 * b1;
            acc[0][2] += a0 * b2; acc[0][3] += a0 * b3;
            acc[1][0] += a1 * b0; acc[1][1] += a1 * b1;
            acc[1][2] += a1 * b2; acc[1][3] += a1 * b3;
        }
        __syncthreads();
    }

    const int hcol = hTile + hcl;
#pragma unroll
    for (int i = 0; i < 2; i++) {
        int b_ = rg * 2 + i;
        size_t zbase = ((size_t)t * Bsz + b_) * NG;
        float zi = acc[i][0] + Z[zbase + 0 * H + hcol];
        float zj = acc[i][1] + Z[zbase + 1 * H + hcol];
        float zf = acc[i][2] + Z[zbase + 2 * H + hcol];
        float zo = acc[i][3] + Z[zbase + 3 * H + hcol];
        float ig = 1.f / (1.f + expf(-zi));
        float fg = 1.f / (1.f + expf(-(zf + 1.f)));
        float og = 1.f / (1.f + expf(-zo));
        float cn = fg * cst[b_ * H + hcol] + ig * tanhf(zj);
        float hn = og * tanhf(cn);
        cst[b_ * H + hcol] = cn;
        hnext[b_ * H + hcol] = hn;
        out[((size_t)b_ * T + t) * (2 * H) + dir * H + hcol] = hn;
    }
}

extern "C" void kernel_launch(void* const* d_in, const int* in_sizes, int n_in,
                              void* d_out, int out_size) {
    const float* x    = (const float*)d_in[0];   // [B,T,D]
    const float* W_fw = (const float*)d_in[1];   // [D+H, 4H]
    const float* b_fw = (const float*)d_in[2];   // [4H]
    const float* W_bw = (const float*)d_in[3];
    const float* b_bw = (const float*)d_in[4];
    float* out = (float*)d_out;                  // [B,T,2H]

    (void)in_sizes; (void)n_in; (void)out_size;

    // zero h/c state
    init_kernel<<<(Bsz * H + 255) / 256, 256>>>();

    // Phase 1: hoisted input projection for both directions
    dim3 g1(4096 / 128, MTOT / 128);   // (32, 256)
    gemm_x_kernel<<<g1, 256>>>(x, W_fw, b_fw, W_bw, b_bw);

    // Phase 2: 512 sequential steps, fw+bw fused per launch
    for (int s = 0; s < T; s++) {
        step_kernel<<<128, 256>>>(s, W_fw, W_bw, out);
    }
}

// round 2
// speedup vs baseline: 1.8321x; 1.8321x over previous
#include <cuda_runtime.h>
#include <math.h>

#define Bsz 64
#define T 512
#define D 512
#define H 512
#define NG 2048  // 4*H
#define MTOT (Bsz*T)  // 32768

// Scratch: hoisted input projections (time-major [T][B][4H]) + recurrent state.
__device__ float g_ZF[(size_t)T * Bsz * NG];   // 268 MB
__device__ float g_ZB[(size_t)T * Bsz * NG];   // 268 MB
__device__ float g_h[2][2][Bsz * H];           // [pingpong][dir][B*H]
__device__ unsigned g_bar[2];                  // per-dir arrival counters

__global__ void init_kernel() {
    int i = blockIdx.x * blockDim.x + threadIdx.x;
    if (i < Bsz * H) {
        g_h[0][0][i] = 0.f; g_h[0][1][i] = 0.f;
        g_h[1][0][i] = 0.f; g_h[1][1][i] = 0.f;
    }
    if (i < 2) g_bar[i] = 0u;
}

// ---------------------------------------------------------------------------
// Phase 1: Z = x @ W[:D] + b for BOTH directions in one GEMM.
// ---------------------------------------------------------------------------
__global__ void __launch_bounds__(256) gemm_x_kernel(
    const float* __restrict__ x,
    const float* __restrict__ Wfw, const float* __restrict__ bfw,
    const float* __restrict__ Wbw, const float* __restrict__ bbw)
{
    __shared__ float As[16][132];
    __shared__ float Bs[16][128];

    const int tid = threadIdx.x;
    const int bm = blockIdx.y * 128;
    const int bn = blockIdx.x * 128;
    const int dir = (bn >= 2048) ? 1 : 0;
    const float* __restrict__ W = dir ? Wbw : Wfw;
    const int n0 = dir ? (bn - 2048) : bn;

    const int tr = tid >> 4;
    const int tc = tid & 15;

    float acc[8][8];
#pragma unroll
    for (int i = 0; i < 8; i++)
#pragma unroll
        for (int j = 0; j < 8; j++) acc[i][j] = 0.f;

    for (int kk = 0; kk < D; kk += 16) {
#pragma unroll
        for (int ld = 0; ld < 2; ld++) {
            int id = tid + ld * 256;
            int ml = id >> 2;
            int k4 = (id & 3) * 4;
            int m = bm + ml;
            int b_ = m & (Bsz - 1);
            int t_ = m >> 6;
            const float4 v = *(const float4*)(x + ((size_t)b_ * T + t_) * D + kk + k4);
            As[k4 + 0][ml] = v.x; As[k4 + 1][ml] = v.y;
            As[k4 + 2][ml] = v.z; As[k4 + 3][ml] = v.w;
        }
#pragma unroll
        for (int ld = 0; ld < 2; ld++) {
            int id = tid + ld * 256;
            int kl = id >> 5;
            int n4 = (id & 31) * 4;
            const float4 v = *(const float4*)(W + (size_t)(kk + kl) * NG + n0 + n4);
            *(float4*)&Bs[kl][n4] = v;
        }
        __syncthreads();
#pragma unroll
        for (int k = 0; k < 16; k++) {
            float a[8], bb[8];
            *(float4*)&a[0] = *(const float4*)&As[k][tr * 8];
            *(float4*)&a[4] = *(const float4*)&As[k][tr * 8 + 4];
            *(float4*)&bb[0] = *(const float4*)&Bs[k][tc * 8];
            *(float4*)&bb[4] = *(const float4*)&Bs[k][tc * 8 + 4];
#pragma unroll
            for (int i = 0; i < 8; i++)
#pragma unroll
                for (int j = 0; j < 8; j++) acc[i][j] += a[i] * bb[j];
        }
        __syncthreads();
    }

    float* __restrict__ Z = dir ? g_ZB : g_ZF;
    const float* __restrict__ bias = dir ? bbw : bfw;
#pragma unroll
    for (int i = 0; i < 8; i++) {
        int m = bm + tr * 8 + i;
#pragma unroll
        for (int j = 0; j < 8; j += 4) {
            int n = n0 + tc * 8 + j;
            float4 v;
            v.x = acc[i][j + 0] + bias[n + 0];
            v.y = acc[i][j + 1] + bias[n + 1];
            v.z = acc[i][j + 2] + bias[n + 2];
            v.w = acc[i][j + 3] + bias[n + 3];
            *(float4*)(Z + (size_t)m * NG + n) = v;
        }
    }
}

// ---------------------------------------------------------------------------
// Phase 2: ONE persistent kernel. 128 blocks (64/dir), 256 threads, 1 blk/SM.
// Block owns 8 h-cols x 4 gates (32 W columns), W slice resident in SMEM.
// Per step: stage h_prev (64x512) in SMEM, 8-way k-split x (8rows x 8cols)
// register microtile GEMM, SMEM reduction, fused gate math, global h write,
// per-direction spin barrier.
// SMEM: Hs 64x516 (132KB, reused as reduction buf) + Ws 512x32 (64KB) + cs.
// ---------------------------------------------------------------------------
#define HS_STRIDE 516
#define HS_FLOATS (Bsz * HS_STRIDE)            // 33024
#define WS_FLOATS (512 * 32)                   // 16384
#define RED_STRIDE 36
#define RED_SEG (Bsz * RED_STRIDE)             // 2304
#define SMEM_FLOATS (HS_FLOATS + WS_FLOATS + 512)
#define SMEM_BYTES (SMEM_FLOATS * 4)           // 199680

__global__ void __launch_bounds__(256, 1) lstm_persistent(
    const float* __restrict__ Wfw, const float* __restrict__ Wbw,
    float* __restrict__ out)
{
    extern __shared__ float sm[];
    float* Hs  = sm;                        // [64][516], overlaid by red after k-loop
    float* red = sm;                        // [8][2304]
    float* Ws  = sm + HS_FLOATS;            // [512][32], col = hcl*4 + gate
    float* cs  = sm + HS_FLOATS + WS_FLOATS;// [64*8] cell state (block-private)

    const int dir   = blockIdx.x >> 6;
    const int hTile = (blockIdx.x & 63) * 8;
    const float* __restrict__ W = dir ? Wbw : Wfw;
    const float* __restrict__ Z = dir ? g_ZB : g_ZF;

    const int tid = threadIdx.x;
    const int ks  = tid >> 5;    // k-split segment 0..7 (= warp id)
    const int tt  = tid & 31;
    const int rowgrp = tt >> 2;  // 0..7 -> rows {rowgrp + 8i}
    const int cg     = tt & 3;   // 0..3 -> hcols {2cg, 2cg+1}

    // Stage recurrent W slice once (resident for all 512 steps)
    for (int i = tid; i < WS_FLOATS; i += 256) {
        int k = i >> 5, col = i & 31;
        int hcl = col >> 2, g = col & 3;
        Ws[i] = W[(size_t)(D + k) * NG + g * H + hTile + hcl];
    }
    for (int i = tid; i < 512; i += 256) cs[i] = 0.f;
    __syncthreads();

    volatile unsigned* bar = &g_bar[dir];

    for (int s = 0; s < T; s++) {
        // Wait until all 64 blocks of this dir finished step s-1
        if (tid == 0 && s > 0) {
            unsigned target = (unsigned)(64 * s);
            while (*bar < target) { }
        }
        __syncthreads();
        __threadfence();

        // Stage h_prev via L2 (__ldcg: ping-pong reuse must not hit stale L1)
        const float* hprev = g_h[s & 1][dir];
        for (int i = tid; i < Bsz * 128; i += 256) {   // 8192 float4
            int row = i >> 7, f4 = i & 127;
            float4 v = __ldcg((const float4*)(hprev + row * 512 + f4 * 4));
            *(float4*)&Hs[row * HS_STRIDE + f4 * 4] = v;
        }
        __syncthreads();

        float acc[8][8];
#pragma unroll
        for (int i = 0; i < 8; i++)
#pragma unroll
            for (int j = 0; j < 8; j++) acc[i][j] = 0.f;

        const int k0 = ks * 64;
#pragma unroll 4
        for (int kq = 0; kq < 64; kq++) {
            int k = k0 + kq;
            float a[8];
#pragma unroll
            for (int i = 0; i < 8; i++) a[i] = Hs[(rowgrp + 8 * i) * HS_STRIDE + k];
            float4 b0 = *(const float4*)&Ws[k * 32 + (cg * 2) * 4];
            float4 b1 = *(const float4*)&Ws[k * 32 + (cg * 2 + 1) * 4];
#pragma unroll
            for (int i = 0; i < 8; i++) {
                acc[i][0] += a[i] * b0.x; acc[i][1] += a[i] * b0.y;
                acc[i][2] += a[i] * b0.z; acc[i][3] += a[i] * b0.w;
                acc[i][4] += a[i] * b1.x; acc[i][5] += a[i] * b1.y;
                acc[i][6] += a[i] * b1.z; acc[i][7] += a[i] * b1.w;
            }
        }
        __syncthreads();   // k-loop done; red may overlay Hs now

        // Dump partials: red[ks][row*36 + hcl*4 + g]
#pragma unroll
        for (int i = 0; i < 8; i++) {
            int row = rowgrp + 8 * i;
            float* dst = &red[ks * RED_SEG + row * RED_STRIDE + (cg * 2) * 4];
            *(float4*)dst       = make_float4(acc[i][0], acc[i][1], acc[i][2], acc[i][3]);
            *(float4*)(dst + 4) = make_float4(acc[i][4], acc[i][5], acc[i][6], acc[i][7]);
        }
        __syncthreads();

        // Epilogue: 2 cells/thread (cell = row*8 + hcl)
        const int t = dir ? (T - 1 - s) : s;
        float* __restrict__ hnext = g_h[(s & 1) ^ 1][dir];
#pragma unroll
        for (int e = 0; e < 2; e++) {
            int cell = tid * 2 + e;
            int row = cell >> 3, hcl = cell & 7;
            float z0 = 0.f, z1 = 0.f, z2 = 0.f, z3 = 0.f;
#pragma unroll
            for (int p = 0; p < 8; p++) {
                float4 v = *(const float4*)&red[p * RED_SEG + row * RED_STRIDE + hcl * 4];
                z0 += v.x; z1 += v.y; z2 += v.z; z3 += v.w;
            }
            const int hcol = hTile + hcl;
            size_t zb = ((size_t)t * Bsz + row) * NG + hcol;
            float zi = z0 + Z[zb];
            float zj = z1 + Z[zb + H];
            float zf = z2 + Z[zb + 2 * H];
            float zo = z3 + Z[zb + 3 * H];
            float ig = 1.f / (1.f + expf(-zi));
            float fg = 1.f / (1.f + expf(-(zf + 1.f)));
            float og = 1.f / (1.f + expf(-zo));
            float cn = fg * cs[cell] + ig * tanhf(zj);
            float hn = og * tanhf(cn);
            cs[cell] = cn;
            hnext[row * H + hcol] = hn;
            out[((size_t)row * T + t) * (2 * H) + dir * H + hcol] = hn;
        }
        __threadfence();
        __syncthreads();
        if (tid == 0) atomicAdd(&g_bar[dir], 1u);
    }
}

extern "C" void kernel_launch(void* const* d_in, const int* in_sizes, int n_in,
                              void* d_out, int out_size) {
    const float* x    = (const float*)d_in[0];   // [B,T,D]
    const float* W_fw = (const float*)d_in[1];   // [D+H, 4H]
    const float* b_fw = (const float*)d_in[2];   // [4H]
    const float* W_bw = (const float*)d_in[3];
    const float* b_bw = (const float*)d_in[4];
    float* out = (float*)d_out;                  // [B,T,2H]

    (void)in_sizes; (void)n_in; (void)out_size;

    cudaFuncSetAttribute(lstm_persistent,
                         cudaFuncAttributeMaxDynamicSharedMemorySize, SMEM_BYTES);

    // zero h/c state + barrier counters (runs on every graph replay)
    init_kernel<<<(Bsz * H + 255) / 256, 256>>>();

    // Phase 1: hoisted input projection for both directions
    dim3 g1(4096 / 128, MTOT / 128);
    gemm_x_kernel<<<g1, 256>>>(x, W_fw, b_fw, W_bw, b_bw);

    // Phase 2: single persistent kernel, 512 steps internal
    lstm_persistent<<<128, 256, SMEM_BYTES>>>(W_fw, W_bw, out);
}

// round 3
// speedup vs baseline: 1.9200x; 1.0480x over previous
#include <cuda_runtime.h>
#include <math.h>

#define Bsz 64
#define T 512
#define D 512
#define H 512
#define NG 2048  // 4*H
#define MTOT (Bsz*T)  // 32768

typedef unsigned long long u64;

// ---- packed f32x2 helpers (Blackwell FFMA2 / FADD2) ----
__device__ __forceinline__ u64 pack_dup(float a) {
    u64 r; unsigned u = __float_as_uint(a);
    asm("mov.b64 %0, {%1, %1};" : "=l"(r) : "r"(u));
    return r;
}
__device__ __forceinline__ void fma2(u64& d, u64 a, u64 b) {
    asm("fma.rn.f32x2 %0, %1, %2, %3;" : "=l"(d) : "l"(a), "l"(b), "l"(d));
}
__device__ __forceinline__ u64 add2(u64 a, u64 b) {
    u64 r; asm("add.rn.f32x2 %0, %1, %2;" : "=l"(r) : "l"(a), "l"(b));
    return r;
}
__device__ __forceinline__ void unpack2(u64 v, float& x, float& y) {
    unsigned a, b;
    asm("mov.b64 {%0, %1}, %2;" : "=r"(a), "=r"(b) : "l"(v));
    x = __uint_as_float(a); y = __uint_as_float(b);
}

// Scratch: hoisted input projections (time-major [T][B][4H]) + recurrent state.
__device__ float g_ZF[(size_t)T * Bsz * NG];   // 268 MB
__device__ float g_ZB[(size_t)T * Bsz * NG];   // 268 MB
__device__ float g_h[2][2][Bsz * H];           // [pingpong][dir][B*H]
__device__ unsigned g_bar[2];                  // per-dir arrival counters

__global__ void init_kernel() {
    int i = blockIdx.x * blockDim.x + threadIdx.x;
    if (i < Bsz * H) {
        g_h[0][0][i] = 0.f; g_h[0][1][i] = 0.f;
        g_h[1][0][i] = 0.f; g_h[1][1][i] = 0.f;
    }
    if (i < 2) g_bar[i] = 0u;
}

// ---------------------------------------------------------------------------
// Phase 1: Z = x @ W[:D] + b for BOTH directions in one GEMM (FFMA2 microtile).
// ---------------------------------------------------------------------------
__global__ void __launch_bounds__(256) gemm_x_kernel(
    const float* __restrict__ x,
    const float* __restrict__ Wfw, const float* __restrict__ bfw,
    const float* __restrict__ Wbw, const float* __restrict__ bbw)
{
    __shared__ float As[16][132];
    __shared__ float Bs[16][128];

    const int tid = threadIdx.x;
    const int bm = blockIdx.y * 128;
    const int bn = blockIdx.x * 128;
    const int dir = (bn >= 2048) ? 1 : 0;
    const float* __restrict__ W = dir ? Wbw : Wfw;
    const int n0 = dir ? (bn - 2048) : bn;

    const int tr = tid >> 4;
    const int tc = tid & 15;

    u64 acc2[8][4];   // col pairs (2j, 2j+1)
#pragma unroll
    for (int i = 0; i < 8; i++)
#pragma unroll
        for (int j = 0; j < 4; j++) acc2[i][j] = 0ull;

    for (int kk = 0; kk < D; kk += 16) {
#pragma unroll
        for (int ld = 0; ld < 2; ld++) {
            int id = tid + ld * 256;
            int ml = id >> 2;
            int k4 = (id & 3) * 4;
            int m = bm + ml;
            int b_ = m & (Bsz - 1);
            int t_ = m >> 6;
            const float4 v = *(const float4*)(x + ((size_t)b_ * T + t_) * D + kk + k4);
            As[k4 + 0][ml] = v.x; As[k4 + 1][ml] = v.y;
            As[k4 + 2][ml] = v.z; As[k4 + 3][ml] = v.w;
        }
#pragma unroll
        for (int ld = 0; ld < 2; ld++) {
            int id = tid + ld * 256;
            int kl = id >> 5;
            int n4 = (id & 31) * 4;
            const float4 v = *(const float4*)(W + (size_t)(kk + kl) * NG + n0 + n4);
            *(float4*)&Bs[kl][n4] = v;
        }
        __syncthreads();
#pragma unroll
        for (int k = 0; k < 16; k++) {
            float a[8];
            *(float4*)&a[0] = *(const float4*)&As[k][tr * 8];
            *(float4*)&a[4] = *(const float4*)&As[k][tr * 8 + 4];
            ulonglong2 bq0 = *(const ulonglong2*)&Bs[k][tc * 8];
            ulonglong2 bq1 = *(const ulonglong2*)&Bs[k][tc * 8 + 4];
#pragma unroll
            for (int i = 0; i < 8; i++) {
                u64 pa = pack_dup(a[i]);
                fma2(acc2[i][0], pa, bq0.x);
                fma2(acc2[i][1], pa, bq0.y);
                fma2(acc2[i][2], pa, bq1.x);
                fma2(acc2[i][3], pa, bq1.y);
            }
        }
        __syncthreads();
    }

    float* __restrict__ Z = dir ? g_ZB : g_ZF;
    const float* __restrict__ bias = dir ? bbw : bfw;
    const int n = n0 + tc * 8;
    ulonglong2 bb0 = *(const ulonglong2*)(bias + n);
    ulonglong2 bb1 = *(const ulonglong2*)(bias + n + 4);
#pragma unroll
    for (int i = 0; i < 8; i++) {
        int m = bm + tr * 8 + i;
        ulonglong2 v0, v1;
        v0.x = add2(acc2[i][0], bb0.x);
        v0.y = add2(acc2[i][1], bb0.y);
        v1.x = add2(acc2[i][2], bb1.x);
        v1.y = add2(acc2[i][3], bb1.y);
        *(ulonglong2*)(Z + (size_t)m * NG + n)     = v0;
        *(ulonglong2*)(Z + (size_t)m * NG + n + 4) = v1;
    }
}

// ---------------------------------------------------------------------------
// Phase 2: ONE persistent kernel, FFMA2 microtile. 128 blocks, 256 thr, 1/SM.
// ---------------------------------------------------------------------------
#define HS_STRIDE 516
#define HS_FLOATS (Bsz * HS_STRIDE)            // 33024
#define WS_FLOATS (512 * 32)                   // 16384
#define RED_STRIDE 36
#define RED_SEG (Bsz * RED_STRIDE)             // 2304
#define SMEM_FLOATS (HS_FLOATS + WS_FLOATS + 512)
#define SMEM_BYTES (SMEM_FLOATS * 4)           // 199680

__global__ void __launch_bounds__(256, 1) lstm_persistent(
    const float* __restrict__ Wfw, const float* __restrict__ Wbw,
    float* __restrict__ out)
{
    extern __shared__ float sm[];
    float* Hs  = sm;                        // [64][516], overlaid by red after k-loop
    float* red = sm;                        // [8][2304]
    float* Ws  = sm + HS_FLOATS;            // [512][32], col = hcl*4 + gate
    float* cs  = sm + HS_FLOATS + WS_FLOATS;// [64*8] cell state (block-private)

    const int dir   = blockIdx.x >> 6;
    const int hTile = (blockIdx.x & 63) * 8;
    const float* __restrict__ W = dir ? Wbw : Wfw;
    const float* __restrict__ Z = dir ? g_ZB : g_ZF;

    const int tid = threadIdx.x;
    const int ks  = tid >> 5;    // k-split segment 0..7 (= warp id)
    const int tt  = tid & 31;
    const int rowgrp = tt >> 2;  // 0..7 -> rows {rowgrp + 8i}
    const int cg     = tt & 3;   // 0..3 -> hcols {2cg, 2cg+1}

    // Stage recurrent W slice once (resident for all 512 steps)
    for (int i = tid; i < WS_FLOATS; i += 256) {
        int k = i >> 5, col = i & 31;
        int hcl = col >> 2, g = col & 3;
        Ws[i] = W[(size_t)(D + k) * NG + g * H + hTile + hcl];
    }
    for (int i = tid; i < 512; i += 256) cs[i] = 0.f;
    __syncthreads();

    volatile unsigned* bar = &g_bar[dir];

    for (int s = 0; s < T; s++) {
        if (tid == 0 && s > 0) {
            unsigned target = (unsigned)(64 * s);
            while (*bar < target) { }
        }
        __syncthreads();
        __threadfence();

        // Stage h_prev via L2 (__ldcg: ping-pong reuse must not hit stale L1)
        const float* hprev = g_h[s & 1][dir];
        for (int i = tid; i < Bsz * 128; i += 256) {   // 8192 float4
            int row = i >> 7, f4 = i & 127;
            float4 v = __ldcg((const float4*)(hprev + row * 512 + f4 * 4));
            *(float4*)&Hs[row * HS_STRIDE + f4 * 4] = v;
        }
        __syncthreads();

        u64 acc2[8][4];   // [row i][colpair]; colpairs = (g0,g1),(g2,g3) x 2 hcols
#pragma unroll
        for (int i = 0; i < 8; i++)
#pragma unroll
            for (int j = 0; j < 4; j++) acc2[i][j] = 0ull;

        const int k0 = ks * 64;
#pragma unroll 4
        for (int kq = 0; kq < 64; kq++) {
            int k = k0 + kq;
            ulonglong2 bq0 = *(const ulonglong2*)&Ws[k * 32 + cg * 8];      // hcol 2cg: (g0,g1),(g2,g3)
            ulonglong2 bq1 = *(const ulonglong2*)&Ws[k * 32 + cg * 8 + 4];  // hcol 2cg+1
#pragma unroll
            for (int i = 0; i < 8; i++) {
                u64 pa = pack_dup(Hs[(rowgrp + 8 * i) * HS_STRIDE + k]);
                fma2(acc2[i][0], pa, bq0.x);
                fma2(acc2[i][1], pa, bq0.y);
                fma2(acc2[i][2], pa, bq1.x);
                fma2(acc2[i][3], pa, bq1.y);
            }
        }
        __syncthreads();   // k-loop done; red may overlay Hs now

        // Dump partials: red[ks][row*36 + hcl*4 + g]
#pragma unroll
        for (int i = 0; i < 8; i++) {
            int row = rowgrp + 8 * i;
            float* dst = &red[ks * RED_SEG + row * RED_STRIDE + cg * 8];
            ulonglong2 v0; v0.x = acc2[i][0]; v0.y = acc2[i][1];
            ulonglong2 v1; v1.x = acc2[i][2]; v1.y = acc2[i][3];
            *(ulonglong2*)dst       = v0;
            *(ulonglong2*)(dst + 4) = v1;
        }
        __syncthreads();

        // Epilogue: 2 cells/thread (cell = row*8 + hcl)
        const int t = dir ? (T - 1 - s) : s;
        float* __restrict__ hnext = g_h[(s & 1) ^ 1][dir];
#pragma unroll
        for (int e = 0; e < 2; e++) {
            int cell = tid * 2 + e;
            int row = cell >> 3, hcl = cell & 7;
            u64 zp01 = 0ull, zp23 = 0ull;
#pragma unroll
            for (int p = 0; p < 8; p++) {
                ulonglong2 v = *(const ulonglong2*)&red[p * RED_SEG + row * RED_STRIDE + hcl * 4];
                zp01 = add2(zp01, v.x);
                zp23 = add2(zp23, v.y);
            }
            float z0, z1, z2, z3;
            unpack2(zp01, z0, z1);
            unpack2(zp23, z2, z3);
            const int hcol = hTile + hcl;
            size_t zb = ((size_t)t * Bsz + row) * NG + hcol;
            float zi = z0 + Z[zb];
            float zj = z1 + Z[zb + H];
            float zf = z2 + Z[zb + 2 * H];
            float zo = z3 + Z[zb + 3 * H];
            float ig = 1.f / (1.f + expf(-zi));
            float fg = 1.f / (1.f + expf(-(zf + 1.f)));
            float og = 1.f / (1.f + expf(-zo));
            float cn = fg * cs[cell] + ig * tanhf(zj);
            float hn = og * tanhf(cn);
            cs[cell] = cn;
            hnext[row * H + hcol] = hn;
            out[((size_t)row * T + t) * (2 * H) + dir * H + hcol] = hn;
        }
        __threadfence();
        __syncthreads();
        if (tid == 0) atomicAdd(&g_bar[dir], 1u);
    }
}

extern "C" void kernel_launch(void* const* d_in, const int* in_sizes, int n_in,
                              void* d_out, int out_size) {
    const float* x    = (const float*)d_in[0];   // [B,T,D]
    const float* W_fw = (const float*)d_in[1];   // [D+H, 4H]
    const float* b_fw = (const float*)d_in[2];   // [4H]
    const float* W_bw = (const float*)d_in[3];
    const float* b_bw = (const float*)d_in[4];
    float* out = (float*)d_out;                  // [B,T,2H]

    (void)in_sizes; (void)n_in; (void)out_size;

    cudaFuncSetAttribute(lstm_persistent,
                         cudaFuncAttributeMaxDynamicSharedMemorySize, SMEM_BYTES);

    init_kernel<<<(Bsz * H + 255) / 256, 256>>>();

    dim3 g1(4096 / 128, MTOT / 128);
    gemm_x_kernel<<<g1, 256>>>(x, W_fw, b_fw, W_bw, b_bw);

    lstm_persistent<<<128, 256, SMEM_BYTES>>>(W_fw, W_bw, out);
}

// round 5
// speedup vs baseline: 2.5163x; 1.3105x over previous
#include <cuda_runtime.h>
#include <cuda_bf16.h>
#include <math.h>

#define Bsz 64
#define T 512
#define D 512
#define H 512
#define NG 2048  // 4*H
#define MTOT (Bsz*T)  // 32768

typedef unsigned long long u64;
typedef unsigned int u32;

// ---- packed f32x2 helpers (phase 1) ----
__device__ __forceinline__ u64 pack_dup(float a) {
    u64 r; unsigned u = __float_as_uint(a);
    asm("mov.b64 %0, {%1, %1};" : "=l"(r) : "r"(u));
    return r;
}
__device__ __forceinline__ void fma2(u64& d, u64 a, u64 b) {
    asm("fma.rn.f32x2 %0, %1, %2, %3;" : "=l"(d) : "l"(a), "l"(b), "l"(d));
}
__device__ __forceinline__ u64 add2(u64 a, u64 b) {
    u64 r; asm("add.rn.f32x2 %0, %1, %2;" : "=l"(r) : "l"(a), "l"(b));
    return r;
}

// ---- mma.sync / ldmatrix helpers (sm_80-era, legal on compute_103) ----
__device__ __forceinline__ u32 smem_u32(const void* p) {
    u32 a;
    asm("{ .reg .u64 t; cvta.to.shared.u64 t, %1; cvt.u32.u64 %0, t; }" : "=r"(a) : "l"(p));
    return a;
}
__device__ __forceinline__ void ldm4(u32* r, u32 p) {
    asm volatile("ldmatrix.sync.aligned.m8n8.x4.shared.b16 {%0,%1,%2,%3}, [%4];"
        : "=r"(r[0]), "=r"(r[1]), "=r"(r[2]), "=r"(r[3]) : "r"(p));
}
__device__ __forceinline__ void mma_bf16(float* d, const u32* a, u32 b0, u32 b1) {
    asm volatile("mma.sync.aligned.m16n8k16.row.col.f32.bf16.bf16.f32 "
        "{%0,%1,%2,%3}, {%4,%5,%6,%7}, {%8,%9}, {%0,%1,%2,%3};"
        : "+f"(d[0]), "+f"(d[1]), "+f"(d[2]), "+f"(d[3])
        : "r"(a[0]), "r"(a[1]), "r"(a[2]), "r"(a[3]), "r"(b0), "r"(b1));
}

__device__ __forceinline__ void split_bf16(float x, unsigned short& hb, unsigned short& lb) {
    __nv_bfloat16 h = __float2bfloat16_rn(x);
    hb = __bfloat16_as_ushort(h);
    lb = __bfloat16_as_ushort(__float2bfloat16_rn(x - __bfloat162float(h)));
}

// Scratch
__device__ float g_ZF[(size_t)T * Bsz * NG];
__device__ float g_ZB[(size_t)T * Bsz * NG];
__device__ __align__(16) __nv_bfloat16 g_hh[2][2][Bsz * H];  // [pingpong][dir] hi
__device__ __align__(16) __nv_bfloat16 g_hl[2][2][Bsz * H];  // lo
__device__ unsigned g_bar[2];

__global__ void init_kernel() {
    int i = blockIdx.x * blockDim.x + threadIdx.x;
    if (i < Bsz * H) {
        __nv_bfloat16 z = __float2bfloat16(0.f);
        g_hh[0][0][i] = z; g_hh[0][1][i] = z; g_hh[1][0][i] = z; g_hh[1][1][i] = z;
        g_hl[0][0][i] = z; g_hl[0][1][i] = z; g_hl[1][0][i] = z; g_hl[1][1][i] = z;
    }
    if (i < 2) g_bar[i] = 0u;
}

// ---------------------------------------------------------------------------
// Phase 1: Z = x @ W[:D] + b (FFMA2 microtile) — unchanged.
// ---------------------------------------------------------------------------
__global__ void __launch_bounds__(256) gemm_x_kernel(
    const float* __restrict__ x,
    const float* __restrict__ Wfw, const float* __restrict__ bfw,
    const float* __restrict__ Wbw, const float* __restrict__ bbw)
{
    __shared__ float As[16][132];
    __shared__ float Bs[16][128];

    const int tid = threadIdx.x;
    const int bm = blockIdx.y * 128;
    const int bn = blockIdx.x * 128;
    const int dir = (bn >= 2048) ? 1 : 0;
    const float* __restrict__ W = dir ? Wbw : Wfw;
    const int n0 = dir ? (bn - 2048) : bn;

    const int tr = tid >> 4;
    const int tc = tid & 15;

    u64 acc2[8][4];
#pragma unroll
    for (int i = 0; i < 8; i++)
#pragma unroll
        for (int j = 0; j < 4; j++) acc2[i][j] = 0ull;

    for (int kk = 0; kk < D; kk += 16) {
#pragma unroll
        for (int ld = 0; ld < 2; ld++) {
            int id = tid + ld * 256;
            int ml = id >> 2;
            int k4 = (id & 3) * 4;
            int m = bm + ml;
            int b_ = m & (Bsz - 1);
            int t_ = m >> 6;
            const float4 v = *(const float4*)(x + ((size_t)b_ * T + t_) * D + kk + k4);
            As[k4 + 0][ml] = v.x; As[k4 + 1][ml] = v.y;
            As[k4 + 2][ml] = v.z; As[k4 + 3][ml] = v.w;
        }
#pragma unroll
        for (int ld = 0; ld < 2; ld++) {
            int id = tid + ld * 256;
            int kl = id >> 5;
            int n4 = (id & 31) * 4;
            const float4 v = *(const float4*)(W + (size_t)(kk + kl) * NG + n0 + n4);
            *(float4*)&Bs[kl][n4] = v;
        }
        __syncthreads();
#pragma unroll
        for (int k = 0; k < 16; k++) {
            float a[8];
            *(float4*)&a[0] = *(const float4*)&As[k][tr * 8];
            *(float4*)&a[4] = *(const float4*)&As[k][tr * 8 + 4];
            ulonglong2 bq0 = *(const ulonglong2*)&Bs[k][tc * 8];
            ulonglong2 bq1 = *(const ulonglong2*)&Bs[k][tc * 8 + 4];
#pragma unroll
            for (int i = 0; i < 8; i++) {
                u64 pa = pack_dup(a[i]);
                fma2(acc2[i][0], pa, bq0.x);
                fma2(acc2[i][1], pa, bq0.y);
                fma2(acc2[i][2], pa, bq1.x);
                fma2(acc2[i][3], pa, bq1.y);
            }
        }
        __syncthreads();
    }

    float* __restrict__ Z = dir ? g_ZB : g_ZF;
    const float* __restrict__ bias = dir ? bbw : bfw;
    const int n = n0 + tc * 8;
    ulonglong2 bb0 = *(const ulonglong2*)(bias + n);
    ulonglong2 bb1 = *(const ulonglong2*)(bias + n + 4);
#pragma unroll
    for (int i = 0; i < 8; i++) {
        int m = bm + tr * 8 + i;
        ulonglong2 v0, v1;
        v0.x = add2(acc2[i][0], bb0.x);
        v0.y = add2(acc2[i][1], bb0.y);
        v1.x = add2(acc2[i][2], bb1.x);
        v1.y = add2(acc2[i][3], bb1.y);
        *(ulonglong2*)(Z + (size_t)m * NG + n)     = v0;
        *(ulonglong2*)(Z + (size_t)m * NG + n + 4) = v1;
    }
}

// ---------------------------------------------------------------------------
// Phase 2: persistent mma.sync kernel. 128 blocks (64/dir), 256 thr, 1/SM.
// A SMEM [64 rows][1024 bf16] = [h_hi | h_lo]   (2048 B/row, XOR-swizzled)
// B SMEM [32 n-rows][1024 bf16] = [W_hi | W_lo] (resident, n = gate*8+hcl)
// Split product: z = Ah*Bh + Al*Bh + Ah*Bl (AlBl dropped, ~2^-16).
// 8 warps: warp = (m-tile 0-3) x (n-half 0-1); 96 k-tiles, 192 mma each.
// Swizzle: 16B chunk cc within a row stored at cc ^ (row & 7).
// ---------------------------------------------------------------------------
#define A_OFF  0
#define B_OFF  131072
#define CS_OFF (B_OFF + 65536)        // 196608
#define P2_SMEM (CS_OFF + 2048 + 64)  // 198720

__global__ void __launch_bounds__(256, 1) lstm_persistent(
    const float* __restrict__ Wfw, const float* __restrict__ Wbw,
    float* __restrict__ out)
{
    extern __shared__ char smem[];
    const u32 sb = smem_u32(smem);
    float* cs = (float*)(smem + CS_OFF);
    float* zb = (float*)(smem + A_OFF);    // [64][34] fp32 overlay, post-MMA only

    const int dir   = blockIdx.x >> 6;
    const int hTile = (blockIdx.x & 63) * 8;
    const float* __restrict__ Wg = dir ? Wbw : Wfw;
    const float* __restrict__ Z  = dir ? g_ZB : g_ZF;

    const int tid = threadIdx.x;
    const int wid = tid >> 5, lane = tid & 31;
    const int mt = wid & 3, nh = wid >> 2;
    const int l7 = lane & 7, sub = lane >> 3;
    const int gr = lane >> 2, tg = lane & 3;

    // ldmatrix lane pointers: x4 matrices must arrive as {a0,a1,a2,a3}/{b0,b1,b2,b3}
    const u32 aRowBase = sb + A_OFF + (u32)(mt * 16 + ((sub & 1) ? 8 : 0) + l7) * 2048;
    const int acbit = sub >> 1;                     // k-chunk low bit (k+8 half)
    const u32 bRowBase = sb + B_OFF + (u32)(nh * 16 + ((sub & 2) ? 8 : 0) + l7) * 2048;
    const int bcbit = sub & 1;
    const int X = l7;                               // swizzle XOR (row & 7)

    // --- Stage W split once (resident all steps): n = gate*8 + hcl ---
    for (int i = tid; i < 32 * 512; i += 256) {
        int n = i >> 9, k = i & 511;
        float wv = Wg[(size_t)(D + k) * NG + (n >> 3) * H + hTile + (n & 7)];
        unsigned short hb, lb; split_bf16(wv, hb, lb);
        u32 off = (u32)n * 2048 + (u32)((((k >> 3) ^ (n & 7)) << 4) + (k & 7) * 2);
        *(unsigned short*)(smem + B_OFF + off)        = hb;   // Bh: chunks 0-63
        *(unsigned short*)(smem + B_OFF + off + 1024) = lb;   // Bl: chunks 64-127
    }
    for (int i = tid; i < 512; i += 256) cs[i] = 0.f;
    __syncthreads();

    volatile unsigned* bar = &g_bar[dir];
    const int erow = tid >> 2;          // epilogue row 0..63
    const int hc0  = (tid & 3) * 2;     // epilogue hcl pair

    for (int s = 0; s < T; s++) {
        if (tid == 0 && s > 0) {
            unsigned target = (unsigned)(64 * s);
            while (*bar < target) { }
        }
        __syncthreads();
        __threadfence();

        const int t = dir ? (T - 1 - s) : s;

        // Z prefetch (in flight across staging + mma)
        float2 zin[4];
        {
            const float* zp = Z + ((size_t)t * Bsz + erow) * NG + hTile + hc0;
#pragma unroll
            for (int g = 0; g < 4; g++)
                zin[g] = __ldcg((const float2*)(zp + g * H));
        }

        // Stage A: pure bf16 copy (no conversion), swizzled
        const __nv_bfloat16* hh = g_hh[s & 1][dir];
        const __nv_bfloat16* hl = g_hl[s & 1][dir];
#pragma unroll
        for (int j = 0; j < 16; j++) {
            int g = tid + j * 256;              // chunk id 0..4095
            int r = g >> 6, kq = g & 63;
            u32 dst = (u32)r * 2048 + (u32)((kq ^ (r & 7)) << 4);
            uint4 vh = __ldcg((const uint4*)(hh + r * 512 + kq * 8));
            uint4 vl = __ldcg((const uint4*)(hl + r * 512 + kq * 8));
            *(uint4*)(smem + A_OFF + dst)        = vh;   // Ah: chunks 0-63
            *(uint4*)(smem + A_OFF + dst + 1024) = vl;   // Al: chunks 64-127
        }
        __syncthreads();

        // MMA: pass 1 = [Ah|Al] x Bh (64 kt), pass 2 = Ah x Bl (32 kt)
        float d0[4] = {0.f, 0.f, 0.f, 0.f}, d1[4] = {0.f, 0.f, 0.f, 0.f};
#pragma unroll 8
        for (int kt = 0; kt < 64; kt++) {
            u32 a[4], b[4];
            u32 pa = aRowBase + (u32)(((((kt << 1) | acbit)) ^ X) << 4);
            u32 pb = bRowBase + (u32)((((((kt & 31) << 1) | bcbit)) ^ X) << 4);
            ldm4(a, pa); ldm4(b, pb);
            mma_bf16(d0, a, b[0], b[1]);
            mma_bf16(d1, a, b[2], b[3]);
        }
#pragma unroll 8
        for (int kt = 0; kt < 32; kt++) {
            u32 a[4], b[4];
            u32 pa = aRowBase + (u32)(((((kt << 1) | acbit)) ^ X) << 4);
            u32 pb = bRowBase + (u32)((((((kt << 1) | bcbit)) + 64) ^ X) << 4);
            ldm4(a, pa); ldm4(b, pb);
            mma_bf16(d0, a, b[0], b[1]);
            mma_bf16(d1, a, b[2], b[3]);
        }
        __syncthreads();   // all A fragment reads done -> zb may overlay A

        // Dump D fragments (rows mt*16+gr / +8; cols gate*8 + tg*2)
        {
            int r0 = mt * 16 + gr;
            int c0 = (nh * 2 + 0) * 8 + tg * 2;
            int c1 = (nh * 2 + 1) * 8 + tg * 2;
            *(float2*)&zb[r0 * 34 + c0]       = make_float2(d0[0], d0[1]);
            *(float2*)&zb[(r0 + 8) * 34 + c0] = make_float2(d0[2], d0[3]);
            *(float2*)&zb[r0 * 34 + c1]       = make_float2(d1[0], d1[1]);
            *(float2*)&zb[(r0 + 8) * 34 + c1] = make_float2(d1[2], d1[3]);
        }
        __syncthreads();

        // Epilogue: 2 cells per thread (erow, hc0/hc0+1)
        float2 zg[4];
#pragma unroll
        for (int g = 0; g < 4; g++)
            zg[g] = *(const float2*)&zb[erow * 34 + g * 8 + hc0];

        float hv[2];
        float* cs2 = &cs[erow * 8 + hc0];
#pragma unroll
        for (int e = 0; e < 2; e++) {
            float zi = (e ? zg[0].y : zg[0].x) + (e ? zin[0].y : zin[0].x);
            float zj = (e ? zg[1].y : zg[1].x) + (e ? zin[1].y : zin[1].x);
            float zf = (e ? zg[2].y : zg[2].x) + (e ? zin[2].y : zin[2].x);
            float zo = (e ? zg[3].y : zg[3].x) + (e ? zin[3].y : zin[3].x);
            float ig = 1.f / (1.f + expf(-zi));
            float fg = 1.f / (1.f + expf(-(zf + 1.f)));
            float og = 1.f / (1.f + expf(-zo));
            float cn = fg * cs2[e] + ig * tanhf(zj);
            float hn = og * tanhf(cn);
            cs2[e] = cn;
            hv[e] = hn;
        }
        {
            unsigned short h0, l0, h1, l1;
            split_bf16(hv[0], h0, l0);
            split_bf16(hv[1], h1, l1);
            int pp = (s & 1) ^ 1;
            u32 off = (u32)erow * 512 + hTile + hc0;
            *(u32*)(&g_hh[pp][dir][off]) = (u32)h0 | ((u32)h1 << 16);
            *(u32*)(&g_hl[pp][dir][off]) = (u32)l0 | ((u32)l1 << 16);
            *(float2*)(out + ((size_t)erow * T + t) * (2 * H) + dir * H + hTile + hc0)
                = make_float2(hv[0], hv[1]);
        }
        __threadfence();
        __syncthreads();
        if (tid == 0) atomicAdd(&g_bar[dir], 1u);
    }
}

extern "C" void kernel_launch(void* const* d_in, const int* in_sizes, int n_in,
                              void* d_out, int out_size) {
    const float* x    = (const float*)d_in[0];
    const float* W_fw = (const float*)d_in[1];
    const float* b_fw = (const float*)d_in[2];
    const float* W_bw = (const float*)d_in[3];
    const float* b_bw = (const float*)d_in[4];
    float* out = (float*)d_out;

    (void)in_sizes; (void)n_in; (void)out_size;

    cudaFuncSetAttribute(lstm_persistent,
                         cudaFuncAttributeMaxDynamicSharedMemorySize, P2_SMEM);

    init_kernel<<<(Bsz * H + 255) / 256, 256>>>();

    dim3 g1(4096 / 128, MTOT / 128);
    gemm_x_kernel<<<g1, 256>>>(x, W_fw, b_fw, W_bw, b_bw);

    lstm_persistent<<<128, 256, P2_SMEM>>>(W_fw, W_bw, out);
}

// round 6
// speedup vs baseline: 3.4079x; 1.3543x over previous
#include <cuda_runtime.h>
#include <cuda_bf16.h>
#include <math.h>

#define Bsz 64
#define T 512
#define D 512
#define H 512
#define NG 2048  // 4*H
#define MTOT (Bsz*T)  // 32768

typedef unsigned long long u64;
typedef unsigned int u32;
typedef unsigned short u16;

// ---- common helpers ----
__device__ __forceinline__ u32 smem_u32(const void* p) {
    u32 a;
    asm("{ .reg .u64 t; cvta.to.shared.u64 t, %1; cvt.u32.u64 %0, t; }" : "=r"(a) : "l"(p));
    return a;
}
__device__ __forceinline__ void ldm4(u32* r, u32 p) {
    asm volatile("ldmatrix.sync.aligned.m8n8.x4.shared.b16 {%0,%1,%2,%3}, [%4];"
        : "=r"(r[0]), "=r"(r[1]), "=r"(r[2]), "=r"(r[3]) : "r"(p));
}
__device__ __forceinline__ void mma_bf16(float* d, const u32* a, u32 b0, u32 b1) {
    asm volatile("mma.sync.aligned.m16n8k16.row.col.f32.bf16.bf16.f32 "
        "{%0,%1,%2,%3}, {%4,%5,%6,%7}, {%8,%9}, {%0,%1,%2,%3};"
        : "+f"(d[0]), "+f"(d[1]), "+f"(d[2]), "+f"(d[3])
        : "r"(a[0]), "r"(a[1]), "r"(a[2]), "r"(a[3]), "r"(b0), "r"(b1));
}
__device__ __forceinline__ void split_bf16(float x, u16& hb, u16& lb) {
    __nv_bfloat16 h = __float2bfloat16_rn(x);
    hb = __bfloat16_as_ushort(h);
    lb = __bfloat16_as_ushort(__float2bfloat16_rn(x - __bfloat162float(h)));
}
// fast sigmoid/tanh via MUFU (ex2.approx rel err ~2^-22)
__device__ __forceinline__ float sigf(float x) {
    float e, r;
    asm("ex2.approx.f32 %0, %1;" : "=f"(e) : "f"(-x * 1.4426950408889634f));
    asm("rcp.approx.f32 %0, %1;" : "=f"(r) : "f"(1.0f + e));
    return r;
}
__device__ __forceinline__ float tanh_fast(float x) {
    return fmaf(2.f, sigf(2.f * x), -1.f);
}
#define CP16(dst, src) \
    asm volatile("cp.async.cg.shared.global [%0], [%1], 16;" :: "r"(dst), "l"(src))
#define CP_COMMIT asm volatile("cp.async.commit_group;")

// ---- scratch ----
__device__ float g_ZF[(size_t)T * Bsz * NG];
__device__ float g_ZB[(size_t)T * Bsz * NG];
__device__ __align__(16) __nv_bfloat16 g_hh[2][2][Bsz * H];
__device__ __align__(16) __nv_bfloat16 g_hl[2][2][Bsz * H];
__device__ __align__(16) __nv_bfloat16 g_xh[(size_t)MTOT * D];   // row m = t*B + b
__device__ __align__(16) __nv_bfloat16 g_xl[(size_t)MTOT * D];
__device__ __align__(16) __nv_bfloat16 g_wth[2][(size_t)NG * 1024]; // [dir][n][k] transposed
__device__ __align__(16) __nv_bfloat16 g_wtl[2][(size_t)NG * 1024];
__device__ unsigned g_bar[2];

__global__ void init_kernel() {
    int i = blockIdx.x * blockDim.x + threadIdx.x;
    if (i < Bsz * H) {
        __nv_bfloat16 z = __float2bfloat16(0.f);
        g_hh[0][0][i] = z; g_hh[0][1][i] = z; g_hh[1][0][i] = z; g_hh[1][1][i] = z;
        g_hl[0][0][i] = z; g_hl[0][1][i] = z; g_hl[1][0][i] = z; g_hl[1][1][i] = z;
    }
    if (i < 2) g_bar[i] = 0u;
}

// split x into hi/lo bf16, reordered to rows m = t*B + b
__global__ void __launch_bounds__(256) split_x_kernel(const float* __restrict__ x) {
    int id = blockIdx.x * 256 + threadIdx.x;        // 0 .. MTOT*64-1
    int m = id >> 6, c8 = id & 63;
    int b = m & (Bsz - 1), t = m >> 6;
    const float4* xp = (const float4*)(x + ((size_t)b * T + t) * D + c8 * 8);
    float4 v0 = xp[0], v1 = xp[1];
    u16 h[8], l[8];
    split_bf16(v0.x, h[0], l[0]); split_bf16(v0.y, h[1], l[1]);
    split_bf16(v0.z, h[2], l[2]); split_bf16(v0.w, h[3], l[3]);
    split_bf16(v1.x, h[4], l[4]); split_bf16(v1.y, h[5], l[5]);
    split_bf16(v1.z, h[6], l[6]); split_bf16(v1.w, h[7], l[7]);
    uint4 ph, pl;
    ph.x = (u32)h[0] | ((u32)h[1] << 16); ph.y = (u32)h[2] | ((u32)h[3] << 16);
    ph.z = (u32)h[4] | ((u32)h[5] << 16); ph.w = (u32)h[6] | ((u32)h[7] << 16);
    pl.x = (u32)l[0] | ((u32)l[1] << 16); pl.y = (u32)l[2] | ((u32)l[3] << 16);
    pl.z = (u32)l[4] | ((u32)l[5] << 16); pl.w = (u32)l[6] | ((u32)l[7] << 16);
    *(uint4*)(g_xh + (size_t)m * D + c8 * 8) = ph;
    *(uint4*)(g_xl + (size_t)m * D + c8 * 8) = pl;
}

// split + transpose W: g_wt[dir][n][k] (n in [0,4H), k in [0,D+H))
__global__ void __launch_bounds__(256) split_w_kernel(
    const float* __restrict__ Wfw, const float* __restrict__ Wbw) {
    __shared__ float tile[32][33];
    int dir = blockIdx.z;
    int k0 = blockIdx.x * 32, n0 = blockIdx.y * 32;
    const float* W = dir ? Wbw : Wfw;
    int tid = threadIdx.x;
#pragma unroll
    for (int i = 0; i < 4; i++) {
        int idx = tid + i * 256;
        int r = idx >> 5, c = idx & 31;
        tile[r][c] = W[(size_t)(k0 + r) * NG + n0 + c];
    }
    __syncthreads();
#pragma unroll
    for (int i = 0; i < 4; i++) {
        int idx = tid + i * 256;
        int r = idx >> 5, c = idx & 31;     // r: n-local, c: k-local
        u16 hb, lb; split_bf16(tile[c][r], hb, lb);
        size_t o = (size_t)(n0 + r) * 1024 + k0 + c;
        g_wth[dir][o] = __ushort_as_bfloat16(hb);
        g_wtl[dir][o] = __ushort_as_bfloat16(lb);
    }
}

// ---------------------------------------------------------------------------
// Phase 1: Z = x @ W[:D] + b, bf16-split mma.sync (AhBh + AlBh + AhBl).
// 128x128x64 tile, 256 thr (8 warps = 4M x 2N, warp 32x64), cp.async 2-stage.
// Buffer layout (64KB): Ah 0 | Al 16K | Bh 32K | Bl 48K; rows 128B, XOR swizzle.
// ---------------------------------------------------------------------------
#define G1_BUF 65536
#define G1_SMEM (2 * G1_BUF)

__global__ void __launch_bounds__(256, 1) gemm_x_mma(
    const float* __restrict__ bfw, const float* __restrict__ bbw)
{
    extern __shared__ char smem[];
    const u32 sb = smem_u32(smem);
    const int tid = threadIdx.x;
    const int wid = tid >> 5, lane = tid & 31;
    const int mw = wid & 3, nw = wid >> 2;
    const int l7 = lane & 7, sub = lane >> 3, gr = lane >> 2, tg = lane & 3;

    const int bm = blockIdx.y * 128;
    const int bn = blockIdx.x * 128;
    const int dir = bn >= 2048;
    const int n0 = bn - dir * 2048;
    const __nv_bfloat16* __restrict__ wth = g_wth[dir];
    const __nv_bfloat16* __restrict__ wtl = g_wtl[dir];

    const int sr = tid >> 3;       // staging row base 0..31
    const int sc = tid & 7;        // staging chunk

    const u32 rowA0 = (u32)(mw * 32 + (sub & 1) * 8 + l7);
    const u32 rowA1 = rowA0 + 16;
    const int acbit = sub >> 1;
    const u32 rB0 = (u32)(nw * 64 + ((sub & 2) ? 8 : 0) + l7);
    const int bcbit = sub & 1;

    float acc[2][8][4];
#pragma unroll
    for (int i = 0; i < 2; i++)
#pragma unroll
        for (int j = 0; j < 8; j++)
#pragma unroll
            for (int q = 0; q < 4; q++) acc[i][j][q] = 0.f;

    // stage chunk kk into buffer base
    auto stage = [&](int kk, u32 base) {
#pragma unroll
        for (int j = 0; j < 4; j++) {
            int r = sr + j * 32;
            u32 dst = base + (u32)(r * 128 + ((sc ^ (r & 7)) << 4));
            size_t ao = (size_t)(bm + r) * D + kk * 64 + sc * 8;
            CP16(dst,          g_xh + ao);
            CP16(dst + 16384,  g_xl + ao);
            size_t bo = (size_t)(n0 + r) * 1024 + kk * 64 + sc * 8;
            CP16(dst + 32768,  wth + bo);
            CP16(dst + 49152,  wtl + bo);
        }
    };

    stage(0, sb);
    CP_COMMIT;

    for (int kk = 0; kk < 8; kk++) {
        u32 buf = sb + (u32)(kk & 1) * G1_BUF;
        if (kk < 7) {
            stage(kk + 1, sb + (u32)((kk + 1) & 1) * G1_BUF);
            CP_COMMIT;
            asm volatile("cp.async.wait_group 1;");
        } else {
            asm volatile("cp.async.wait_group 0;");
        }
        __syncthreads();
#pragma unroll
        for (int q = 0; q < 4; q++) {
            int ca = 2 * q + acbit;
            u32 a0[4], a1[4], al0[4], al1[4];
            u32 aoff0 = rowA0 * 128 + (u32)((ca ^ (rowA0 & 7)) << 4);
            u32 aoff1 = rowA1 * 128 + (u32)((ca ^ (rowA1 & 7)) << 4);
            ldm4(a0,  buf + aoff0);
            ldm4(a1,  buf + aoff1);
            ldm4(al0, buf + 16384 + aoff0);
            ldm4(al1, buf + 16384 + aoff1);
            int cb = 2 * q + bcbit;
#pragma unroll
            for (int j = 0; j < 4; j++) {
                u32 rB = rB0 + (u32)(j * 16);
                u32 boff = rB * 128 + (u32)((cb ^ (rB & 7)) << 4);
                u32 bh[4], bl[4];
                ldm4(bh, buf + 32768 + boff);
                ldm4(bl, buf + 49152 + boff);
                mma_bf16(acc[0][2*j],   a0,  bh[0], bh[1]);
                mma_bf16(acc[0][2*j+1], a0,  bh[2], bh[3]);
                mma_bf16(acc[1][2*j],   a1,  bh[0], bh[1]);
                mma_bf16(acc[1][2*j+1], a1,  bh[2], bh[3]);
                mma_bf16(acc[0][2*j],   al0, bh[0], bh[1]);
                mma_bf16(acc[0][2*j+1], al0, bh[2], bh[3]);
                mma_bf16(acc[1][2*j],   al1, bh[0], bh[1]);
                mma_bf16(acc[1][2*j+1], al1, bh[2], bh[3]);
                mma_bf16(acc[0][2*j],   a0,  bl[0], bl[1]);
                mma_bf16(acc[0][2*j+1], a0,  bl[2], bl[3]);
                mma_bf16(acc[1][2*j],   a1,  bl[0], bl[1]);
                mma_bf16(acc[1][2*j+1], a1,  bl[2], bl[3]);
            }
        }
        __syncthreads();
    }

    float* __restrict__ Zo = dir ? g_ZB : g_ZF;
    const float* __restrict__ bias = dir ? bbw : bfw;
#pragma unroll
    for (int am = 0; am < 2; am++) {
        int m0 = bm + mw * 32 + am * 16 + gr;
#pragma unroll
        for (int p = 0; p < 8; p++) {
            int nc = n0 + nw * 64 + p * 8 + tg * 2;
            float bx = bias[nc], by = bias[nc + 1];
            const float* a = acc[am][p];
            *(float2*)(Zo + (size_t)m0 * NG + nc)       = make_float2(a[0] + bx, a[1] + by);
            *(float2*)(Zo + (size_t)(m0 + 8) * NG + nc) = make_float2(a[2] + bx, a[3] + by);
        }
    }
}

// ---------------------------------------------------------------------------
// Phase 2: persistent mma.sync kernel, fused fragment epilogue.
// A [64r][2048B]=[Ah|Al], B [32n][2048B]=[Wh|Wl]; nh0 warps own gates i,j;
// nh1 warps own gates f,o; P = sig(i)*tanh(j) handed off via 2KB SMEM.
// ---------------------------------------------------------------------------
#define A_OFF2 0
#define B_OFF2 131072
#define CS_OFF2 (B_OFF2 + 65536)       // 2048 B cell state
#define SP_OFF2 (CS_OFF2 + 2048)       // 2048 B P handoff
#define P2_SMEM (SP_OFF2 + 2048 + 64)

__global__ void __launch_bounds__(256, 1) lstm_persistent(float* __restrict__ out)
{
    extern __shared__ char smem[];
    const u32 sb = smem_u32(smem);
    float* cs = (float*)(smem + CS_OFF2);
    float* sP = (float*)(smem + SP_OFF2);

    const int dir   = blockIdx.x >> 6;
    const int hTile = (blockIdx.x & 63) * 8;
    const float* __restrict__ Z = dir ? g_ZB : g_ZF;
    const __nv_bfloat16* __restrict__ wth = g_wth[dir];
    const __nv_bfloat16* __restrict__ wtl = g_wtl[dir];

    const int tid = threadIdx.x;
    const int wid = tid >> 5, lane = tid & 31;
    const int mt = wid & 3, nh = wid >> 2;
    const int l7 = lane & 7, sub = lane >> 3;
    const int gr = lane >> 2, tg = lane & 3;

    const u32 aRowBase = sb + A_OFF2 + (u32)(mt * 16 + ((sub & 1) ? 8 : 0) + l7) * 2048;
    const int acbit = sub >> 1;
    const u32 bRowBase = sb + B_OFF2 + (u32)(nh * 16 + ((sub & 2) ? 8 : 0) + l7) * 2048;
    const int bcbit = sub & 1;
    const int X = l7;

    // Stage W slice (straight copy from pre-split transposed arrays)
    for (int i = tid; i < 32 * 64; i += 256) {
        int n = i >> 6, kq = i & 63;
        int ng = (n >> 3) * H + hTile + (n & 7);
        uint4 vh = *(const uint4*)(wth + (size_t)ng * 1024 + 512 + kq * 8);
        uint4 vl = *(const uint4*)(wtl + (size_t)ng * 1024 + 512 + kq * 8);
        u32 dst = (u32)(n * 2048 + ((kq ^ (n & 7)) << 4));
        *(uint4*)(smem + B_OFF2 + dst)        = vh;
        *(uint4*)(smem + B_OFF2 + dst + 1024) = vl;
    }
    for (int i = tid; i < 512; i += 256) cs[i] = 0.f;
    __syncthreads();

    volatile unsigned* bar = &g_bar[dir];
    const int R0 = mt * 16 + gr;
    const int C0 = tg * 2;
    const int g0 = nh * 2;

    for (int s = 0; s < T; s++) {
        if (tid == 0 && s > 0) {
            unsigned target = (unsigned)(64 * s);
            while (*bar < target) { }
        }
        __syncthreads();
        __threadfence();

        const int t = dir ? (T - 1 - s) : s;

        // Z prefetch: this thread's 4 cells, its 2 gates
        const float* zp = Z + ((size_t)t * Bsz + R0) * NG + g0 * H + hTile + C0;
        float2 zA0 = __ldcg((const float2*)zp);
        float2 zB0 = __ldcg((const float2*)(zp + H));
        float2 zA1 = __ldcg((const float2*)(zp + 8 * NG));
        float2 zB1 = __ldcg((const float2*)(zp + 8 * NG + H));

        // Stage A (bf16 hi/lo straight copy)
        const __nv_bfloat16* hh = g_hh[s & 1][dir];
        const __nv_bfloat16* hl = g_hl[s & 1][dir];
#pragma unroll
        for (int j = 0; j < 16; j++) {
            int g = tid + j * 256;
            int r = g >> 6, kq = g & 63;
            u32 dst = (u32)(r * 2048 + ((kq ^ (r & 7)) << 4));
            uint4 vh = __ldcg((const uint4*)(hh + r * 512 + kq * 8));
            uint4 vl = __ldcg((const uint4*)(hl + r * 512 + kq * 8));
            *(uint4*)(smem + A_OFF2 + dst)        = vh;
            *(uint4*)(smem + A_OFF2 + dst + 1024) = vl;
        }
        __syncthreads();

        // MMA: pass 1 = [Ah|Al] x Bh (64 kt), pass 2 = Ah x Bl (32 kt)
        float d0[4] = {0.f, 0.f, 0.f, 0.f}, d1[4] = {0.f, 0.f, 0.f, 0.f};
#pragma unroll 8
        for (int kt = 0; kt < 64; kt++) {
            u32 a[4], b[4];
            u32 pa = aRowBase + (u32)(((((kt << 1) | acbit)) ^ X) << 4);
            u32 pb = bRowBase + (u32)((((((kt & 31) << 1) | bcbit)) ^ X) << 4);
            ldm4(a, pa); ldm4(b, pb);
            mma_bf16(d0, a, b[0], b[1]);
            mma_bf16(d1, a, b[2], b[3]);
        }
#pragma unroll 8
        for (int kt = 0; kt < 32; kt++) {
            u32 a[4], b[4];
            u32 pa = aRowBase + (u32)(((((kt << 1) | acbit)) ^ X) << 4);
            u32 pb = bRowBase + (u32)((((((kt << 1) | bcbit)) + 64) ^ X) << 4);
            ldm4(a, pa); ldm4(b, pb);
            mma_bf16(d0, a, b[0], b[1]);
            mma_bf16(d1, a, b[2], b[3]);
        }

        // Fused epilogue: nh0 -> P = sig(i)*tanh(j); nh1 -> F,O then c/h
        float Fv[4], Ov[4];
        if (nh == 0) {
            float2 p0, p1;
            p0.x = sigf(d0[0] + zA0.x) * tanh_fast(d1[0] + zB0.x);
            p0.y = sigf(d0[1] + zA0.y) * tanh_fast(d1[1] + zB0.y);
            p1.x = sigf(d0[2] + zA1.x) * tanh_fast(d1[2] + zB1.x);
            p1.y = sigf(d0[3] + zA1.y) * tanh_fast(d1[3] + zB1.y);
            *(float2*)&sP[R0 * 8 + C0]       = p0;
            *(float2*)&sP[(R0 + 8) * 8 + C0] = p1;
        } else {
            Fv[0] = sigf(d0[0] + zA0.x + 1.f); Fv[1] = sigf(d0[1] + zA0.y + 1.f);
            Fv[2] = sigf(d0[2] + zA1.x + 1.f); Fv[3] = sigf(d0[3] + zA1.y + 1.f);
            Ov[0] = sigf(d1[0] + zB0.x); Ov[1] = sigf(d1[1] + zB0.y);
            Ov[2] = sigf(d1[2] + zB1.x); Ov[3] = sigf(d1[3] + zB1.y);
        }
        __syncthreads();

        if (nh == 1) {
            float2 P0 = *(const float2*)&sP[R0 * 8 + C0];
            float2 P1 = *(const float2*)&sP[(R0 + 8) * 8 + C0];
            float2 c0 = *(const float2*)&cs[R0 * 8 + C0];
            float2 c1 = *(const float2*)&cs[(R0 + 8) * 8 + C0];
            float cn0x = Fv[0] * c0.x + P0.x, cn0y = Fv[1] * c0.y + P0.y;
            float cn1x = Fv[2] * c1.x + P1.x, cn1y = Fv[3] * c1.y + P1.y;
            *(float2*)&cs[R0 * 8 + C0]       = make_float2(cn0x, cn0y);
            *(float2*)&cs[(R0 + 8) * 8 + C0] = make_float2(cn1x, cn1y);
            float h0x = Ov[0] * tanh_fast(cn0x), h0y = Ov[1] * tanh_fast(cn0y);
            float h1x = Ov[2] * tanh_fast(cn1x), h1y = Ov[3] * tanh_fast(cn1y);

            u16 ha0, la0, ha1, la1, hb0, lb0, hb1, lb1;
            split_bf16(h0x, ha0, la0); split_bf16(h0y, ha1, la1);
            split_bf16(h1x, hb0, lb0); split_bf16(h1y, hb1, lb1);
            int pp = (s & 1) ^ 1;
            u32 o0 = (u32)(R0 * H + hTile + C0);
            u32 o1 = (u32)((R0 + 8) * H + hTile + C0);
            *(u32*)&g_hh[pp][dir][o0] = (u32)ha0 | ((u32)ha1 << 16);
            *(u32*)&g_hl[pp][dir][o0] = (u32)la0 | ((u32)la1 << 16);
            *(u32*)&g_hh[pp][dir][o1] = (u32)hb0 | ((u32)hb1 << 16);
            *(u32*)&g_hl[pp][dir][o1] = (u32)lb0 | ((u32)lb1 << 16);
            *(float2*)(out + ((size_t)R0 * T + t) * (2 * H) + dir * H + hTile + C0)
                = make_float2(h0x, h0y);
            *(float2*)(out + ((size_t)(R0 + 8) * T + t) * (2 * H) + dir * H + hTile + C0)
                = make_float2(h1x, h1y);
        }
        __threadfence();
        __syncthreads();
        if (tid == 0) atomicAdd(&g_bar[dir], 1u);
    }
}

extern "C" void kernel_launch(void* const* d_in, const int* in_sizes, int n_in,
                              void* d_out, int out_size) {
    const float* x    = (const float*)d_in[0];
    const float* W_fw = (const float*)d_in[1];
    const float* b_fw = (const float*)d_in[2];
    const float* W_bw = (const float*)d_in[3];
    const float* b_bw = (const float*)d_in[4];
    float* out = (float*)d_out;

    (void)in_sizes; (void)n_in; (void)out_size;

    cudaFuncSetAttribute(gemm_x_mma,
                         cudaFuncAttributeMaxDynamicSharedMemorySize, G1_SMEM);
    cudaFuncSetAttribute(lstm_persistent,
                         cudaFuncAttributeMaxDynamicSharedMemorySize, P2_SMEM);

    init_kernel<<<(Bsz * H + 255) / 256, 256>>>();
    split_x_kernel<<<MTOT * 64 / 256, 256>>>(x);
    split_w_kernel<<<dim3(32, 64, 2), 256>>>(W_fw, W_bw);

    gemm_x_mma<<<dim3(32, 256), 256, G1_SMEM>>>(b_fw, b_bw);

    lstm_persistent<<<128, 256, P2_SMEM>>>(out);
}

// round 7
// speedup vs baseline: 4.5593x; 1.3379x over previous
#include <cuda_runtime.h>
#include <cuda_bf16.h>
#include <math.h>

#define Bsz 64
#define T 512
#define D 512
#define H 512
#define NG 2048  // 4*H
#define MTOT (Bsz*T)  // 32768

typedef unsigned long long u64;
typedef unsigned int u32;
typedef unsigned short u16;

// ---- common helpers ----
__device__ __forceinline__ u32 smem_u32(const void* p) {
    u32 a;
    asm("{ .reg .u64 t; cvta.to.shared.u64 t, %1; cvt.u32.u64 %0, t; }" : "=r"(a) : "l"(p));
    return a;
}
__device__ __forceinline__ void ldm4(u32* r, u32 p) {
    asm volatile("ldmatrix.sync.aligned.m8n8.x4.shared.b16 {%0,%1,%2,%3}, [%4];"
        : "=r"(r[0]), "=r"(r[1]), "=r"(r[2]), "=r"(r[3]) : "r"(p));
}
__device__ __forceinline__ void mma_bf16(float* d, const u32* a, u32 b0, u32 b1) {
    asm volatile("mma.sync.aligned.m16n8k16.row.col.f32.bf16.bf16.f32 "
        "{%0,%1,%2,%3}, {%4,%5,%6,%7}, {%8,%9}, {%0,%1,%2,%3};"
        : "+f"(d[0]), "+f"(d[1]), "+f"(d[2]), "+f"(d[3])
        : "r"(a[0]), "r"(a[1]), "r"(a[2]), "r"(a[3]), "r"(b0), "r"(b1));
}
__device__ __forceinline__ void split_bf16(float x, u16& hb, u16& lb) {
    __nv_bfloat16 h = __float2bfloat16_rn(x);
    hb = __bfloat16_as_ushort(h);
    lb = __bfloat16_as_ushort(__float2bfloat16_rn(x - __bfloat162float(h)));
}
__device__ __forceinline__ float sigf(float x) {
    float e, r;
    asm("ex2.approx.f32 %0, %1;" : "=f"(e) : "f"(-x * 1.4426950408889634f));
    asm("rcp.approx.f32 %0, %1;" : "=f"(r) : "f"(1.0f + e));
    return r;
}
__device__ __forceinline__ float tanh_fast(float x) {
    return fmaf(2.f, sigf(2.f * x), -1.f);
}
__device__ __forceinline__ void red_release_add(unsigned* p, unsigned v) {
    asm volatile("red.release.gpu.global.add.u32 [%0], %1;" :: "l"(p), "r"(v) : "memory");
}
__device__ __forceinline__ unsigned ld_acquire(const unsigned* p) {
    unsigned v;
    asm volatile("ld.acquire.gpu.global.u32 %0, [%1];" : "=r"(v) : "l"(p) : "memory");
    return v;
}
#define CP16(dst, src) \
    asm volatile("cp.async.cg.shared.global [%0], [%1], 16;" :: "r"(dst), "l"(src))
#define CP_COMMIT asm volatile("cp.async.commit_group;")

// ---- scratch ----
__device__ float g_ZF[(size_t)T * Bsz * NG];
__device__ float g_ZB[(size_t)T * Bsz * NG];
__device__ __align__(16) __nv_bfloat16 g_hh[2][2][Bsz * H];
__device__ __align__(16) __nv_bfloat16 g_hl[2][2][Bsz * H];
__device__ __align__(16) __nv_bfloat16 g_xh[(size_t)MTOT * D];   // row m = t*B + b
__device__ __align__(16) __nv_bfloat16 g_xl[(size_t)MTOT * D];
__device__ __align__(16) __nv_bfloat16 g_wth[2][(size_t)NG * 1024]; // [dir][n][k]
__device__ __align__(16) __nv_bfloat16 g_wtl[2][(size_t)NG * 1024];
__device__ unsigned g_bar[2];

__global__ void init_kernel() {
    int i = blockIdx.x * blockDim.x + threadIdx.x;
    if (i < Bsz * H) {
        __nv_bfloat16 z = __float2bfloat16(0.f);
        g_hh[0][0][i] = z; g_hh[0][1][i] = z; g_hh[1][0][i] = z; g_hh[1][1][i] = z;
        g_hl[0][0][i] = z; g_hl[0][1][i] = z; g_hl[1][0][i] = z; g_hl[1][1][i] = z;
    }
    if (i < 2) g_bar[i] = 0u;
}

__global__ void __launch_bounds__(256) split_x_kernel(const float* __restrict__ x) {
    int id = blockIdx.x * 256 + threadIdx.x;
    int m = id >> 6, c8 = id & 63;
    int b = m & (Bsz - 1), t = m >> 6;
    const float4* xp = (const float4*)(x + ((size_t)b * T + t) * D + c8 * 8);
    float4 v0 = xp[0], v1 = xp[1];
    u16 h[8], l[8];
    split_bf16(v0.x, h[0], l[0]); split_bf16(v0.y, h[1], l[1]);
    split_bf16(v0.z, h[2], l[2]); split_bf16(v0.w, h[3], l[3]);
    split_bf16(v1.x, h[4], l[4]); split_bf16(v1.y, h[5], l[5]);
    split_bf16(v1.z, h[6], l[6]); split_bf16(v1.w, h[7], l[7]);
    uint4 ph, pl;
    ph.x = (u32)h[0] | ((u32)h[1] << 16); ph.y = (u32)h[2] | ((u32)h[3] << 16);
    ph.z = (u32)h[4] | ((u32)h[5] << 16); ph.w = (u32)h[6] | ((u32)h[7] << 16);
    pl.x = (u32)l[0] | ((u32)l[1] << 16); pl.y = (u32)l[2] | ((u32)l[3] << 16);
    pl.z = (u32)l[4] | ((u32)l[5] << 16); pl.w = (u32)l[6] | ((u32)l[7] << 16);
    *(uint4*)(g_xh + (size_t)m * D + c8 * 8) = ph;
    *(uint4*)(g_xl + (size_t)m * D + c8 * 8) = pl;
}

__global__ void __launch_bounds__(256) split_w_kernel(
    const float* __restrict__ Wfw, const float* __restrict__ Wbw) {
    __shared__ float tile[32][33];
    int dir = blockIdx.z;
    int k0 = blockIdx.x * 32, n0 = blockIdx.y * 32;
    const float* W = dir ? Wbw : Wfw;
    int tid = threadIdx.x;
#pragma unroll
    for (int i = 0; i < 4; i++) {
        int idx = tid + i * 256;
        int r = idx >> 5, c = idx & 31;
        tile[r][c] = W[(size_t)(k0 + r) * NG + n0 + c];
    }
    __syncthreads();
#pragma unroll
    for (int i = 0; i < 4; i++) {
        int idx = tid + i * 256;
        int r = idx >> 5, c = idx & 31;
        u16 hb, lb; split_bf16(tile[c][r], hb, lb);
        size_t o = (size_t)(n0 + r) * 1024 + k0 + c;
        g_wth[dir][o] = __ushort_as_bfloat16(hb);
        g_wtl[dir][o] = __ushort_as_bfloat16(lb);
    }
}

// ---------------------------------------------------------------------------
// Phase 1: Z = x @ W[:D] + b, bf16-split mma.sync — unchanged from round 6.
// ---------------------------------------------------------------------------
#define G1_BUF 65536
#define G1_SMEM (2 * G1_BUF)

__global__ void __launch_bounds__(256, 1) gemm_x_mma(
    const float* __restrict__ bfw, const float* __restrict__ bbw)
{
    extern __shared__ char smem[];
    const u32 sb = smem_u32(smem);
    const int tid = threadIdx.x;
    const int wid = tid >> 5, lane = tid & 31;
    const int mw = wid & 3, nw = wid >> 2;
    const int l7 = lane & 7, sub = lane >> 3, gr = lane >> 2, tg = lane & 3;

    const int bm = blockIdx.y * 128;
    const int bn = blockIdx.x * 128;
    const int dir = bn >= 2048;
    const int n0 = bn - dir * 2048;
    const __nv_bfloat16* __restrict__ wth = g_wth[dir];
    const __nv_bfloat16* __restrict__ wtl = g_wtl[dir];

    const int sr = tid >> 3;
    const int sc = tid & 7;

    const u32 rowA0 = (u32)(mw * 32 + (sub & 1) * 8 + l7);
    const u32 rowA1 = rowA0 + 16;
    const int acbit = sub >> 1;
    const u32 rB0 = (u32)(nw * 64 + ((sub & 2) ? 8 : 0) + l7);
    const int bcbit = sub & 1;

    float acc[2][8][4];
#pragma unroll
    for (int i = 0; i < 2; i++)
#pragma unroll
        for (int j = 0; j < 8; j++)
#pragma unroll
            for (int q = 0; q < 4; q++) acc[i][j][q] = 0.f;

    auto stage = [&](int kk, u32 base) {
#pragma unroll
        for (int j = 0; j < 4; j++) {
            int r = sr + j * 32;
            u32 dst = base + (u32)(r * 128 + ((sc ^ (r & 7)) << 4));
            size_t ao = (size_t)(bm + r) * D + kk * 64 + sc * 8;
            CP16(dst,          g_xh + ao);
            CP16(dst + 16384,  g_xl + ao);
            size_t bo = (size_t)(n0 + r) * 1024 + kk * 64 + sc * 8;
            CP16(dst + 32768,  wth + bo);
            CP16(dst + 49152,  wtl + bo);
        }
    };

    stage(0, sb);
    CP_COMMIT;

    for (int kk = 0; kk < 8; kk++) {
        u32 buf = sb + (u32)(kk & 1) * G1_BUF;
        if (kk < 7) {
            stage(kk + 1, sb + (u32)((kk + 1) & 1) * G1_BUF);
            CP_COMMIT;
            asm volatile("cp.async.wait_group 1;");
        } else {
            asm volatile("cp.async.wait_group 0;");
        }
        __syncthreads();
#pragma unroll
        for (int q = 0; q < 4; q++) {
            int ca = 2 * q + acbit;
            u32 a0[4], a1[4], al0[4], al1[4];
            u32 aoff0 = rowA0 * 128 + (u32)((ca ^ (rowA0 & 7)) << 4);
            u32 aoff1 = rowA1 * 128 + (u32)((ca ^ (rowA1 & 7)) << 4);
            ldm4(a0,  buf + aoff0);
            ldm4(a1,  buf + aoff1);
            ldm4(al0, buf + 16384 + aoff0);
            ldm4(al1, buf + 16384 + aoff1);
            int cb = 2 * q + bcbit;
#pragma unroll
            for (int j = 0; j < 4; j++) {
                u32 rB = rB0 + (u32)(j * 16);
                u32 boff = rB * 128 + (u32)((cb ^ (rB & 7)) << 4);
                u32 bh[4], bl[4];
                ldm4(bh, buf + 32768 + boff);
                ldm4(bl, buf + 49152 + boff);
                mma_bf16(acc[0][2*j],   a0,  bh[0], bh[1]);
                mma_bf16(acc[0][2*j+1], a0,  bh[2], bh[3]);
                mma_bf16(acc[1][2*j],   a1,  bh[0], bh[1]);
                mma_bf16(acc[1][2*j+1], a1,  bh[2], bh[3]);
                mma_bf16(acc[0][2*j],   al0, bh[0], bh[1]);
                mma_bf16(acc[0][2*j+1], al0, bh[2], bh[3]);
                mma_bf16(acc[1][2*j],   al1, bh[0], bh[1]);
                mma_bf16(acc[1][2*j+1], al1, bh[2], bh[3]);
                mma_bf16(acc[0][2*j],   a0,  bl[0], bl[1]);
                mma_bf16(acc[0][2*j+1], a0,  bl[2], bl[3]);
                mma_bf16(acc[1][2*j],   a1,  bl[0], bl[1]);
                mma_bf16(acc[1][2*j+1], a1,  bl[2], bl[3]);
            }
        }
        __syncthreads();
    }

    float* __restrict__ Zo = dir ? g_ZB : g_ZF;
    const float* __restrict__ bias = dir ? bbw : bfw;
#pragma unroll
    for (int am = 0; am < 2; am++) {
        int m0 = bm + mw * 32 + am * 16 + gr;
#pragma unroll
        for (int p = 0; p < 8; p++) {
            int nc = n0 + nw * 64 + p * 8 + tg * 2;
            float bx = bias[nc], by = bias[nc + 1];
            const float* a = acc[am][p];
            *(float2*)(Zo + (size_t)m0 * NG + nc)       = make_float2(a[0] + bx, a[1] + by);
            *(float2*)(Zo + (size_t)(m0 + 8) * NG + nc) = make_float2(a[2] + bx, a[3] + by);
        }
    }
}

// ---------------------------------------------------------------------------
// Phase 2 v2: 128 blocks = dir x rowgrp(2) x hgrp(32). Block owns 32 batch
// rows x 16 hcols. A = 32 rows x [Ah|Al] (64KB staged/step via cp.async);
// B = 64 n-rows x [Wh|Wl] (128KB resident). Warp = (mw 0-1) x (q 0-3);
// q covers 2 gates x 8 hcols: q even -> (i,j), q odd -> (f,o), hcl half q>>1.
// Fused epilogue via 1-float P handoff. release/acquire barrier, no membar.
// ---------------------------------------------------------------------------
#define A_OFF2 0
#define B_OFF2 65536
#define CS_OFF2 (B_OFF2 + 131072)      // 196608, 2KB cell state (32x16)
#define SP_OFF2 (CS_OFF2 + 2048)       // 2KB P handoff
#define P2_SMEM (SP_OFF2 + 2048 + 64)

__global__ void __launch_bounds__(256, 1) lstm_persistent(float* __restrict__ out)
{
    extern __shared__ char smem[];
    const u32 sb = smem_u32(smem);
    float* cs = (float*)(smem + CS_OFF2);
    float* sP = (float*)(smem + SP_OFF2);

    const int dir   = blockIdx.x >> 6;
    const int rg    = (blockIdx.x >> 5) & 1;
    const int hTile = (blockIdx.x & 31) * 16;
    const float* __restrict__ Z = dir ? g_ZB : g_ZF;
    const __nv_bfloat16* __restrict__ wth = g_wth[dir];
    const __nv_bfloat16* __restrict__ wtl = g_wtl[dir];

    const int tid = threadIdx.x;
    const int wid = tid >> 5, lane = tid & 31;
    const int mw = wid & 1, q = wid >> 1;
    const int l7 = lane & 7, sub = lane >> 3;
    const int gr = lane >> 2, tg = lane & 3;

    const u32 aRowBase = sb + A_OFF2 + (u32)(mw * 16 + ((sub & 1) ? 8 : 0) + l7) * 2048;
    const int acbit = sub >> 1;
    const u32 bRowBase = sb + B_OFF2 + (u32)(q * 16 + ((sub & 2) ? 8 : 0) + l7) * 2048;
    const int bcbit = sub & 1;
    const int X = l7;

    // Stage B (resident): n = q16*16 + g2*8 + hc8 -> gate=(q16&1)*2+g2, hcl=(q16>>1)*8+hc8
    for (int i = tid; i < 64 * 64; i += 256) {
        int n = i >> 6, kq = i & 63;
        int q16 = n >> 4, g2 = (n >> 3) & 1, hc8 = n & 7;
        int gate = (q16 & 1) * 2 + g2;
        int hcl = (q16 >> 1) * 8 + hc8;
        size_t ng = (size_t)(gate * H + hTile + hcl) * 1024 + 512 + kq * 8;
        uint4 vh = *(const uint4*)(wth + ng);
        uint4 vl = *(const uint4*)(wtl + ng);
        u32 dst = (u32)(n * 2048 + ((kq ^ (n & 7)) << 4));
        *(uint4*)(smem + B_OFF2 + dst)        = vh;
        *(uint4*)(smem + B_OFF2 + dst + 1024) = vl;
    }
    for (int i = tid; i < 512; i += 256) cs[i] = 0.f;
    __syncthreads();

    unsigned* bar = &g_bar[dir];
    const int R0 = mw * 16 + gr;             // local row 0..31
    const int hcl0 = (q >> 1) * 8 + tg * 2;  // hcol-local pair base
    const int nh = q & 1;                    // 0: gates i,j  1: gates f,o
    const int g0 = nh * 2;

    for (int s = 0; s < T; s++) {
        if (tid == 0 && s > 0) {
            unsigned target = (unsigned)(256 * s);
            while (ld_acquire(bar) < target) { }
        }
        __syncthreads();

        const int t = dir ? (T - 1 - s) : s;
        const int grow = rg * 32 + R0;

        // Z prefetch for this thread's 4 cells x its 2 gates
        const float* zp = Z + ((size_t)t * Bsz + grow) * NG + g0 * H + hTile + hcl0;
        float2 zA0 = __ldcg((const float2*)zp);
        float2 zB0 = __ldcg((const float2*)(zp + H));
        float2 zA1 = __ldcg((const float2*)(zp + 8 * NG));
        float2 zB1 = __ldcg((const float2*)(zp + 8 * NG + H));

        // Stage A (32 rows x 64KB) via cp.async
        const __nv_bfloat16* hh = g_hh[s & 1][dir] + rg * 32 * H;
        const __nv_bfloat16* hl = g_hl[s & 1][dir] + rg * 32 * H;
#pragma unroll
        for (int j = 0; j < 8; j++) {
            int g = tid + j * 256;            // 0..2047
            int r = g >> 6, kq = g & 63;
            u32 dst = sb + A_OFF2 + (u32)(r * 2048 + ((kq ^ (r & 7)) << 4));
            CP16(dst,        hh + r * 512 + kq * 8);
            CP16(dst + 1024, hl + r * 512 + kq * 8);
        }
        CP_COMMIT;
        asm volatile("cp.async.wait_group 0;");
        __syncthreads();

        // MMA: per kt: 4 ldm4 (Ah, Al, Bh, Bl), 6 mma -> (Ah+Al)Bh + AhBl
        float d0[4] = {0.f, 0.f, 0.f, 0.f}, d1[4] = {0.f, 0.f, 0.f, 0.f};
#pragma unroll 8
        for (int kt = 0; kt < 32; kt++) {
            int ca = (kt << 1) | acbit;
            int cb = (kt << 1) | bcbit;
            u32 ah[4], al[4], bh[4], bl[4];
            ldm4(ah, aRowBase + (u32)((ca ^ X) << 4));
            ldm4(al, aRowBase + (u32)(((ca + 64) ^ X) << 4));
            ldm4(bh, bRowBase + (u32)((cb ^ X) << 4));
            ldm4(bl, bRowBase + (u32)(((cb + 64) ^ X) << 4));
            mma_bf16(d0, ah, bh[0], bh[1]);
            mma_bf16(d1, ah, bh[2], bh[3]);
            mma_bf16(d0, al, bh[0], bh[1]);
            mma_bf16(d1, al, bh[2], bh[3]);
            mma_bf16(d0, ah, bl[0], bl[1]);
            mma_bf16(d1, ah, bl[2], bl[3]);
        }

        // Epilogue: nh0 -> P = sig(i)*tanh(j); nh1 -> F,O then c/h
        float Fv[4], Ov[4];
        if (nh == 0) {
            float2 p0, p1;
            p0.x = sigf(d0[0] + zA0.x) * tanh_fast(d1[0] + zB0.x);
            p0.y = sigf(d0[1] + zA0.y) * tanh_fast(d1[1] + zB0.y);
            p1.x = sigf(d0[2] + zA1.x) * tanh_fast(d1[2] + zB1.x);
            p1.y = sigf(d0[3] + zA1.y) * tanh_fast(d1[3] + zB1.y);
            *(float2*)&sP[R0 * 16 + hcl0]       = p0;
            *(float2*)&sP[(R0 + 8) * 16 + hcl0] = p1;
        } else {
            Fv[0] = sigf(d0[0] + zA0.x + 1.f); Fv[1] = sigf(d0[1] + zA0.y + 1.f);
            Fv[2] = sigf(d0[2] + zA1.x + 1.f); Fv[3] = sigf(d0[3] + zA1.y + 1.f);
            Ov[0] = sigf(d1[0] + zB0.x); Ov[1] = sigf(d1[1] + zB0.y);
            Ov[2] = sigf(d1[2] + zB1.x); Ov[3] = sigf(d1[3] + zB1.y);
        }
        __syncthreads();

        if (nh == 1) {
            float2 P0 = *(const float2*)&sP[R0 * 16 + hcl0];
            float2 P1 = *(const float2*)&sP[(R0 + 8) * 16 + hcl0];
            float2 c0 = *(const float2*)&cs[R0 * 16 + hcl0];
            float2 c1 = *(const float2*)&cs[(R0 + 8) * 16 + hcl0];
            float cn0x = Fv[0] * c0.x + P0.x, cn0y = Fv[1] * c0.y + P0.y;
            float cn1x = Fv[2] * c1.x + P1.x, cn1y = Fv[3] * c1.y + P1.y;
            *(float2*)&cs[R0 * 16 + hcl0]       = make_float2(cn0x, cn0y);
            *(float2*)&cs[(R0 + 8) * 16 + hcl0] = make_float2(cn1x, cn1y);
            float h0x = Ov[0] * tanh_fast(cn0x), h0y = Ov[1] * tanh_fast(cn0y);
            float h1x = Ov[2] * tanh_fast(cn1x), h1y = Ov[3] * tanh_fast(cn1y);

            u16 ha0, la0, ha1, la1, hb0, lb0, hb1, lb1;
            split_bf16(h0x, ha0, la0); split_bf16(h0y, ha1, la1);
            split_bf16(h1x, hb0, lb0); split_bf16(h1y, hb1, lb1);
            int pp = (s & 1) ^ 1;
            u32 o0 = (u32)(grow * H + hTile + hcl0);
            u32 o1 = o0 + 8 * H;
            *(u32*)&g_hh[pp][dir][o0] = (u32)ha0 | ((u32)ha1 << 16);
            *(u32*)&g_hl[pp][dir][o0] = (u32)la0 | ((u32)la1 << 16);
            *(u32*)&g_hh[pp][dir][o1] = (u32)hb0 | ((u32)hb1 << 16);
            *(u32*)&g_hl[pp][dir][o1] = (u32)lb0 | ((u32)lb1 << 16);
            *(float2*)(out + ((size_t)grow * T + t) * (2 * H) + dir * H + hTile + hcl0)
                = make_float2(h0x, h0y);
            *(float2*)(out + ((size_t)(grow + 8) * T + t) * (2 * H) + dir * H + hTile + hcl0)
                = make_float2(h1x, h1y);

            // Per-warp arrival: h-stores ordered by syncwarp + release (cumulative)
            __syncwarp();
            if (lane == 0) red_release_add(bar, 1u);
        }
    }
}

extern "C" void kernel_launch(void* const* d_in, const int* in_sizes, int n_in,
                              void* d_out, int out_size) {
    const float* x    = (const float*)d_in[0];
    const float* W_fw = (const float*)d_in[1];
    const float* b_fw = (const float*)d_in[2];
    const float* W_bw = (const float*)d_in[3];
    const float* b_bw = (const float*)d_in[4];
    float* out = (float*)d_out;

    (void)in_sizes; (void)n_in; (void)out_size;

    cudaFuncSetAttribute(gemm_x_mma,
                         cudaFuncAttributeMaxDynamicSharedMemorySize, G1_SMEM);
    cudaFuncSetAttribute(lstm_persistent,
                         cudaFuncAttributeMaxDynamicSharedMemorySize, P2_SMEM);

    init_kernel<<<(Bsz * H + 255) / 256, 256>>>();
    split_x_kernel<<<MTOT * 64 / 256, 256>>>(x);
    split_w_kernel<<<dim3(32, 64, 2), 256>>>(W_fw, W_bw);

    gemm_x_mma<<<dim3(32, 256), 256, G1_SMEM>>>(b_fw, b_bw);

    lstm_persistent<<<128, 256, P2_SMEM>>>(out);
}

// round 8
// speedup vs baseline: 4.6192x; 1.0131x over previous
#include <cuda_runtime.h>
#include <cuda_bf16.h>
#include <math.h>

#define Bsz 64
#define T 512
#define D 512
#define H 512
#define NG 2048  // 4*H
#define MTOT (Bsz*T)  // 32768

typedef unsigned long long u64;
typedef unsigned int u32;
typedef unsigned short u16;

// ---- common helpers ----
__device__ __forceinline__ u32 smem_u32(const void* p) {
    u32 a;
    asm("{ .reg .u64 t; cvta.to.shared.u64 t, %1; cvt.u32.u64 %0, t; }" : "=r"(a) : "l"(p));
    return a;
}
__device__ __forceinline__ void ldm4(u32* r, u32 p) {
    asm volatile("ldmatrix.sync.aligned.m8n8.x4.shared.b16 {%0,%1,%2,%3}, [%4];"
        : "=r"(r[0]), "=r"(r[1]), "=r"(r[2]), "=r"(r[3]) : "r"(p));
}
__device__ __forceinline__ void mma_bf16(float* d, const u32* a, u32 b0, u32 b1) {
    asm volatile("mma.sync.aligned.m16n8k16.row.col.f32.bf16.bf16.f32 "
        "{%0,%1,%2,%3}, {%4,%5,%6,%7}, {%8,%9}, {%0,%1,%2,%3};"
        : "+f"(d[0]), "+f"(d[1]), "+f"(d[2]), "+f"(d[3])
        : "r"(a[0]), "r"(a[1]), "r"(a[2]), "r"(a[3]), "r"(b0), "r"(b1));
}
__device__ __forceinline__ void split_bf16(float x, u16& hb, u16& lb) {
    __nv_bfloat16 h = __float2bfloat16_rn(x);
    hb = __bfloat16_as_ushort(h);
    lb = __bfloat16_as_ushort(__float2bfloat16_rn(x - __bfloat162float(h)));
}
__device__ __forceinline__ float sigf(float x) {
    float e, r;
    asm("ex2.approx.f32 %0, %1;" : "=f"(e) : "f"(-x * 1.4426950408889634f));
    asm("rcp.approx.f32 %0, %1;" : "=f"(r) : "f"(1.0f + e));
    return r;
}
__device__ __forceinline__ float tanh_fast(float x) {
    return fmaf(2.f, sigf(2.f * x), -1.f);
}
__device__ __forceinline__ void red_release_add(unsigned* p, unsigned v) {
    asm volatile("red.release.gpu.global.add.u32 [%0], %1;" :: "l"(p), "r"(v) : "memory");
}
__device__ __forceinline__ unsigned ld_acquire(const unsigned* p) {
    unsigned v;
    asm volatile("ld.acquire.gpu.global.u32 %0, [%1];" : "=r"(v) : "l"(p) : "memory");
    return v;
}
#define CP16(dst, src) \
    asm volatile("cp.async.cg.shared.global [%0], [%1], 16;" :: "r"(dst), "l"(src))
#define CP_COMMIT asm volatile("cp.async.commit_group;")
#define BAR_SYNC(id, cnt) asm volatile("bar.sync %0, %1;" :: "r"(id), "r"(cnt) : "memory")

// ---- scratch ----
__device__ float g_ZF[(size_t)T * Bsz * NG];
__device__ float g_ZB[(size_t)T * Bsz * NG];
__device__ __align__(16) __nv_bfloat16 g_hh[2][2][Bsz * H];
__device__ __align__(16) __nv_bfloat16 g_hl[2][2][Bsz * H];
__device__ __align__(16) __nv_bfloat16 g_xh[(size_t)MTOT * D];   // row m = t*B + b
__device__ __align__(16) __nv_bfloat16 g_xl[(size_t)MTOT * D];
__device__ __align__(16) __nv_bfloat16 g_wth[2][(size_t)NG * 1024]; // [dir][n][k]
__device__ __align__(16) __nv_bfloat16 g_wtl[2][(size_t)NG * 1024];
__device__ unsigned g_bar2[2][2];      // [dir][rg]

__global__ void init_kernel() {
    int i = blockIdx.x * blockDim.x + threadIdx.x;
    if (i < Bsz * H) {
        __nv_bfloat16 z = __float2bfloat16(0.f);
        g_hh[0][0][i] = z; g_hh[0][1][i] = z; g_hh[1][0][i] = z; g_hh[1][1][i] = z;
        g_hl[0][0][i] = z; g_hl[0][1][i] = z; g_hl[1][0][i] = z; g_hl[1][1][i] = z;
    }
    if (i < 2) { g_bar2[i][0] = 0u; g_bar2[i][1] = 0u; }
}

__global__ void __launch_bounds__(256) split_x_kernel(const float* __restrict__ x) {
    int id = blockIdx.x * 256 + threadIdx.x;
    int m = id >> 6, c8 = id & 63;
    int b = m & (Bsz - 1), t = m >> 6;
    const float4* xp = (const float4*)(x + ((size_t)b * T + t) * D + c8 * 8);
    float4 v0 = xp[0], v1 = xp[1];
    u16 h[8], l[8];
    split_bf16(v0.x, h[0], l[0]); split_bf16(v0.y, h[1], l[1]);
    split_bf16(v0.z, h[2], l[2]); split_bf16(v0.w, h[3], l[3]);
    split_bf16(v1.x, h[4], l[4]); split_bf16(v1.y, h[5], l[5]);
    split_bf16(v1.z, h[6], l[6]); split_bf16(v1.w, h[7], l[7]);
    uint4 ph, pl;
    ph.x = (u32)h[0] | ((u32)h[1] << 16); ph.y = (u32)h[2] | ((u32)h[3] << 16);
    ph.z = (u32)h[4] | ((u32)h[5] << 16); ph.w = (u32)h[6] | ((u32)h[7] << 16);
    pl.x = (u32)l[0] | ((u32)l[1] << 16); pl.y = (u32)l[2] | ((u32)l[3] << 16);
    pl.z = (u32)l[4] | ((u32)l[5] << 16); pl.w = (u32)l[6] | ((u32)l[7] << 16);
    *(uint4*)(g_xh + (size_t)m * D + c8 * 8) = ph;
    *(uint4*)(g_xl + (size_t)m * D + c8 * 8) = pl;
}

__global__ void __launch_bounds__(256) split_w_kernel(
    const float* __restrict__ Wfw, const float* __restrict__ Wbw) {
    __shared__ float tile[32][33];
    int dir = blockIdx.z;
    int k0 = blockIdx.x * 32, n0 = blockIdx.y * 32;
    const float* W = dir ? Wbw : Wfw;
    int tid = threadIdx.x;
#pragma unroll
    for (int i = 0; i < 4; i++) {
        int idx = tid + i * 256;
        int r = idx >> 5, c = idx & 31;
        tile[r][c] = W[(size_t)(k0 + r) * NG + n0 + c];
    }
    __syncthreads();
#pragma unroll
    for (int i = 0; i < 4; i++) {
        int idx = tid + i * 256;
        int r = idx >> 5, c = idx & 31;
        u16 hb, lb; split_bf16(tile[c][r], hb, lb);
        size_t o = (size_t)(n0 + r) * 1024 + k0 + c;
        g_wth[dir][o] = __ushort_as_bfloat16(hb);
        g_wtl[dir][o] = __ushort_as_bfloat16(lb);
    }
}

// ---------------------------------------------------------------------------
// Phase 1: Z = x @ W[:D] + b, bf16-split mma.sync — unchanged.
// ---------------------------------------------------------------------------
#define G1_BUF 65536
#define G1_SMEM (2 * G1_BUF)

__global__ void __launch_bounds__(256, 1) gemm_x_mma(
    const float* __restrict__ bfw, const float* __restrict__ bbw)
{
    extern __shared__ char smem[];
    const u32 sb = smem_u32(smem);
    const int tid = threadIdx.x;
    const int wid = tid >> 5, lane = tid & 31;
    const int mw = wid & 3, nw = wid >> 2;
    const int l7 = lane & 7, sub = lane >> 3, gr = lane >> 2, tg = lane & 3;

    const int bm = blockIdx.y * 128;
    const int bn = blockIdx.x * 128;
    const int dir = bn >= 2048;
    const int n0 = bn - dir * 2048;
    const __nv_bfloat16* __restrict__ wth = g_wth[dir];
    const __nv_bfloat16* __restrict__ wtl = g_wtl[dir];

    const int sr = tid >> 3;
    const int sc = tid & 7;

    const u32 rowA0 = (u32)(mw * 32 + (sub & 1) * 8 + l7);
    const u32 rowA1 = rowA0 + 16;
    const int acbit = sub >> 1;
    const u32 rB0 = (u32)(nw * 64 + ((sub & 2) ? 8 : 0) + l7);
    const int bcbit = sub & 1;

    float acc[2][8][4];
#pragma unroll
    for (int i = 0; i < 2; i++)
#pragma unroll
        for (int j = 0; j < 8; j++)
#pragma unroll
            for (int q = 0; q < 4; q++) acc[i][j][q] = 0.f;

    auto stage = [&](int kk, u32 base) {
#pragma unroll
        for (int j = 0; j < 4; j++) {
            int r = sr + j * 32;
            u32 dst = base + (u32)(r * 128 + ((sc ^ (r & 7)) << 4));
            size_t ao = (size_t)(bm + r) * D + kk * 64 + sc * 8;
            CP16(dst,          g_xh + ao);
            CP16(dst + 16384,  g_xl + ao);
            size_t bo = (size_t)(n0 + r) * 1024 + kk * 64 + sc * 8;
            CP16(dst + 32768,  wth + bo);
            CP16(dst + 49152,  wtl + bo);
        }
    };

    stage(0, sb);
    CP_COMMIT;

    for (int kk = 0; kk < 8; kk++) {
        u32 buf = sb + (u32)(kk & 1) * G1_BUF;
        if (kk < 7) {
            stage(kk + 1, sb + (u32)((kk + 1) & 1) * G1_BUF);
            CP_COMMIT;
            asm volatile("cp.async.wait_group 1;");
        } else {
            asm volatile("cp.async.wait_group 0;");
        }
        __syncthreads();
#pragma unroll
        for (int q = 0; q < 4; q++) {
            int ca = 2 * q + acbit;
            u32 a0[4], a1[4], al0[4], al1[4];
            u32 aoff0 = rowA0 * 128 + (u32)((ca ^ (rowA0 & 7)) << 4);
            u32 aoff1 = rowA1 * 128 + (u32)((ca ^ (rowA1 & 7)) << 4);
            ldm4(a0,  buf + aoff0);
            ldm4(a1,  buf + aoff1);
            ldm4(al0, buf + 16384 + aoff0);
            ldm4(al1, buf + 16384 + aoff1);
            int cb = 2 * q + bcbit;
#pragma unroll
            for (int j = 0; j < 4; j++) {
                u32 rB = rB0 + (u32)(j * 16);
                u32 boff = rB * 128 + (u32)((cb ^ (rB & 7)) << 4);
                u32 bh[4], bl[4];
                ldm4(bh, buf + 32768 + boff);
                ldm4(bl, buf + 49152 + boff);
                mma_bf16(acc[0][2*j],   a0,  bh[0], bh[1]);
                mma_bf16(acc[0][2*j+1], a0,  bh[2], bh[3]);
                mma_bf16(acc[1][2*j],   a1,  bh[0], bh[1]);
                mma_bf16(acc[1][2*j+1], a1,  bh[2], bh[3]);
                mma_bf16(acc[0][2*j],   al0, bh[0], bh[1]);
                mma_bf16(acc[0][2*j+1], al0, bh[2], bh[3]);
                mma_bf16(acc[1][2*j],   al1, bh[0], bh[1]);
                mma_bf16(acc[1][2*j+1], al1, bh[2], bh[3]);
                mma_bf16(acc[0][2*j],   a0,  bl[0], bl[1]);
                mma_bf16(acc[0][2*j+1], a0,  bl[2], bl[3]);
                mma_bf16(acc[1][2*j],   a1,  bl[0], bl[1]);
                mma_bf16(acc[1][2*j+1], a1,  bl[2], bl[3]);
            }
        }
        __syncthreads();
    }

    float* __restrict__ Zo = dir ? g_ZB : g_ZF;
    const float* __restrict__ bias = dir ? bbw : bfw;
#pragma unroll
    for (int am = 0; am < 2; am++) {
        int m0 = bm + mw * 32 + am * 16 + gr;
#pragma unroll
        for (int p = 0; p < 8; p++) {
            int nc = n0 + nw * 64 + p * 8 + tg * 2;
            float bx = bias[nc], by = bias[nc + 1];
            const float* a = acc[am][p];
            *(float2*)(Zo + (size_t)m0 * NG + nc)       = make_float2(a[0] + bx, a[1] + by);
            *(float2*)(Zo + (size_t)(m0 + 8) * NG + nc) = make_float2(a[2] + bx, a[3] + by);
        }
    }
}

// ---------------------------------------------------------------------------
// Phase 2 v3: no CTA-wide barriers in the step loop.
// 128 blocks = dir x rg(2) x hg(32); block = 32 rows x 16 hcols.
// - all-lane acquire spin on g_bar2[dir][rg] (128 arrivals/step)
// - A staged per mw-half by its own 4 reader warps; bar.sync(1+mw,128)
// - P handoff via pair barrier bar.sync(3+mw*2+(q>>1),64)
// - out stores after the release
// Safety: passing the spin implies own-block nh1 released step s-1, which
// (transitively through pair barriers) implies all 8 warps finished their
// prior mma/A-reads -> staging cannot race prior readers.
// ---------------------------------------------------------------------------
#define A_OFF2 0
#define B_OFF2 65536
#define CS_OFF2 (B_OFF2 + 131072)      // 2KB cell state (32x16)
#define SP_OFF2 (CS_OFF2 + 2048)       // 2KB P handoff
#define P2_SMEM (SP_OFF2 + 2048 + 64)

__global__ void __launch_bounds__(256, 1) lstm_persistent(float* __restrict__ out)
{
    extern __shared__ char smem[];
    const u32 sb = smem_u32(smem);
    float* cs = (float*)(smem + CS_OFF2);
    float* sP = (float*)(smem + SP_OFF2);

    const int dir   = blockIdx.x >> 6;
    const int rg    = (blockIdx.x >> 5) & 1;
    const int hTile = (blockIdx.x & 31) * 16;
    const float* __restrict__ Z = dir ? g_ZB : g_ZF;
    const __nv_bfloat16* __restrict__ wth = g_wth[dir];
    const __nv_bfloat16* __restrict__ wtl = g_wtl[dir];

    const int tid = threadIdx.x;
    const int wid = tid >> 5, lane = tid & 31;
    const int mw = wid & 1, q = wid >> 1;
    const int l7 = lane & 7, sub = lane >> 3;
    const int gr = lane >> 2, tg = lane & 3;

    const u32 aRowBase = sb + A_OFF2 + (u32)(mw * 16 + ((sub & 1) ? 8 : 0) + l7) * 2048;
    const int acbit = sub >> 1;
    const u32 bRowBase = sb + B_OFF2 + (u32)(q * 16 + ((sub & 2) ? 8 : 0) + l7) * 2048;
    const int bcbit = sub & 1;
    const int X = l7;

    // Stage B (resident): n = q16*16 + g2*8 + hc8 -> gate=(q16&1)*2+g2, hcl=(q16>>1)*8+hc8
    for (int i = tid; i < 64 * 64; i += 256) {
        int n = i >> 6, kq = i & 63;
        int q16 = n >> 4, g2 = (n >> 3) & 1, hc8 = n & 7;
        int gate = (q16 & 1) * 2 + g2;
        int hcl = (q16 >> 1) * 8 + hc8;
        size_t ng = (size_t)(gate * H + hTile + hcl) * 1024 + 512 + kq * 8;
        uint4 vh = *(const uint4*)(wth + ng);
        uint4 vl = *(const uint4*)(wtl + ng);
        u32 dst = (u32)(n * 2048 + ((kq ^ (n & 7)) << 4));
        *(uint4*)(smem + B_OFF2 + dst)        = vh;
        *(uint4*)(smem + B_OFF2 + dst + 1024) = vl;
    }
    for (int i = tid; i < 512; i += 256) cs[i] = 0.f;
    __syncthreads();

    unsigned* bar = &g_bar2[dir][rg];
    const int R0 = mw * 16 + gr;             // local row 0..31
    const int hcl0 = (q >> 1) * 8 + tg * 2;  // hcol-local pair base
    const int nh = q & 1;                    // 0: gates i,j  1: gates f,o
    const int g0 = nh * 2;
    const int hidx = (wid >> 1) * 32 + lane; // index within mw-half (0..127)
    const int halfbar = 1 + mw;
    const int pairbar = 3 + mw * 2 + (q >> 1);

    for (int s = 0; s < T; s++) {
        if (s > 0) {
            unsigned target = 128u * (unsigned)s;
            while (ld_acquire(bar) < target) { }
        }

        const int t = dir ? (T - 1 - s) : s;
        const int grow = rg * 32 + R0;

        // Z prefetch for this thread's 4 cells x its 2 gates
        const float* zp = Z + ((size_t)t * Bsz + grow) * NG + g0 * H + hTile + hcl0;
        float2 zA0 = __ldcg((const float2*)zp);
        float2 zB0 = __ldcg((const float2*)(zp + H));
        float2 zA1 = __ldcg((const float2*)(zp + 8 * NG));
        float2 zB1 = __ldcg((const float2*)(zp + 8 * NG + H));

        // Stage A: each mw-half stages its own 16 rows (32KB hi+lo)
        {
            const __nv_bfloat16* hh = g_hh[s & 1][dir] + (rg * 32 + mw * 16) * H;
            const __nv_bfloat16* hl = g_hl[s & 1][dir] + (rg * 32 + mw * 16) * H;
#pragma unroll
            for (int j = 0; j < 8; j++) {
                int g = hidx + j * 128;          // 0..1023
                int r = g >> 6, kq = g & 63;     // r: 0..15 local
                int rfull = mw * 16 + r;
                u32 dst = sb + A_OFF2 + (u32)(rfull * 2048 + ((kq ^ (rfull & 7)) << 4));
                CP16(dst,        hh + r * 512 + kq * 8);
                CP16(dst + 1024, hl + r * 512 + kq * 8);
            }
        }
        CP_COMMIT;
        asm volatile("cp.async.wait_group 0;");
        BAR_SYNC(halfbar, 128);

        // MMA: per kt: 4 ldm4 (Ah, Al, Bh, Bl), 6 mma -> (Ah+Al)Bh + AhBl
        float d0[4] = {0.f, 0.f, 0.f, 0.f}, d1[4] = {0.f, 0.f, 0.f, 0.f};
#pragma unroll 8
        for (int kt = 0; kt < 32; kt++) {
            int ca = (kt << 1) | acbit;
            int cb = (kt << 1) | bcbit;
            u32 ah[4], al[4], bh[4], bl[4];
            ldm4(ah, aRowBase + (u32)((ca ^ X) << 4));
            ldm4(al, aRowBase + (u32)(((ca + 64) ^ X) << 4));
            ldm4(bh, bRowBase + (u32)((cb ^ X) << 4));
            ldm4(bl, bRowBase + (u32)(((cb + 64) ^ X) << 4));
            mma_bf16(d0, ah, bh[0], bh[1]);
            mma_bf16(d1, ah, bh[2], bh[3]);
            mma_bf16(d0, al, bh[0], bh[1]);
            mma_bf16(d1, al, bh[2], bh[3]);
            mma_bf16(d0, ah, bl[0], bl[1]);
            mma_bf16(d1, ah, bl[2], bl[3]);
        }

        // Epilogue: nh0 -> P = sig(i)*tanh(j); pair barrier; nh1 -> c/h
        if (nh == 0) {
            float2 p0, p1;
            p0.x = sigf(d0[0] + zA0.x) * tanh_fast(d1[0] + zB0.x);
            p0.y = sigf(d0[1] + zA0.y) * tanh_fast(d1[1] + zB0.y);
            p1.x = sigf(d0[2] + zA1.x) * tanh_fast(d1[2] + zB1.x);
            p1.y = sigf(d0[3] + zA1.y) * tanh_fast(d1[3] + zB1.y);
            *(float2*)&sP[R0 * 16 + hcl0]       = p0;
            *(float2*)&sP[(R0 + 8) * 16 + hcl0] = p1;
            BAR_SYNC(pairbar, 64);
        } else {
            float Fv[4], Ov[4];
            Fv[0] = sigf(d0[0] + zA0.x + 1.f); Fv[1] = sigf(d0[1] + zA0.y + 1.f);
            Fv[2] = sigf(d0[2] + zA1.x + 1.f); Fv[3] = sigf(d0[3] + zA1.y + 1.f);
            Ov[0] = sigf(d1[0] + zB0.x); Ov[1] = sigf(d1[1] + zB0.y);
            Ov[2] = sigf(d1[2] + zB1.x); Ov[3] = sigf(d1[3] + zB1.y);
            BAR_SYNC(pairbar, 64);

            float2 P0 = *(const float2*)&sP[R0 * 16 + hcl0];
            float2 P1 = *(const float2*)&sP[(R0 + 8) * 16 + hcl0];
            float2 c0 = *(const float2*)&cs[R0 * 16 + hcl0];
            float2 c1 = *(const float2*)&cs[(R0 + 8) * 16 + hcl0];
            float cn0x = Fv[0] * c0.x + P0.x, cn0y = Fv[1] * c0.y + P0.y;
            float cn1x = Fv[2] * c1.x + P1.x, cn1y = Fv[3] * c1.y + P1.y;
            *(float2*)&cs[R0 * 16 + hcl0]       = make_float2(cn0x, cn0y);
            *(float2*)&cs[(R0 + 8) * 16 + hcl0] = make_float2(cn1x, cn1y);
            float h0x = Ov[0] * tanh_fast(cn0x), h0y = Ov[1] * tanh_fast(cn0y);
            float h1x = Ov[2] * tanh_fast(cn1x), h1y = Ov[3] * tanh_fast(cn1y);

            u16 ha0, la0, ha1, la1, hb0, lb0, hb1, lb1;
            split_bf16(h0x, ha0, la0); split_bf16(h0y, ha1, la1);
            split_bf16(h1x, hb0, lb0); split_bf16(h1y, hb1, lb1);
            int pp = (s & 1) ^ 1;
            u32 o0 = (u32)(grow * H + hTile + hcl0);
            u32 o1 = o0 + 8 * H;
            *(u32*)&g_hh[pp][dir][o0] = (u32)ha0 | ((u32)ha1 << 16);
            *(u32*)&g_hl[pp][dir][o0] = (u32)la0 | ((u32)la1 << 16);
            *(u32*)&g_hh[pp][dir][o1] = (u32)hb0 | ((u32)hb1 << 16);
            *(u32*)&g_hl[pp][dir][o1] = (u32)lb0 | ((u32)lb1 << 16);

            __syncwarp();
            if (lane == 0) red_release_add(bar, 1u);

            // out stores off the critical path (after release)
            *(float2*)(out + ((size_t)grow * T + t) * (2 * H) + dir * H + hTile + hcl0)
                = make_float2(h0x, h0y);
            *(float2*)(out + ((size_t)(grow + 8) * T + t) * (2 * H) + dir * H + hTile + hcl0)
                = make_float2(h1x, h1y);
        }
    }
}

extern "C" void kernel_launch(void* const* d_in, const int* in_sizes, int n_in,
                              void* d_out, int out_size) {
    const float* x    = (const float*)d_in[0];
    const float* W_fw = (const float*)d_in[1];
    const float* b_fw = (const float*)d_in[2];
    const float* W_bw = (const float*)d_in[3];
    const float* b_bw = (const float*)d_in[4];
    float* out = (float*)d_out;

    (void)in_sizes; (void)n_in; (void)out_size;

    cudaFuncSetAttribute(gemm_x_mma,
                         cudaFuncAttributeMaxDynamicSharedMemorySize, G1_SMEM);
    cudaFuncSetAttribute(lstm_persistent,
                         cudaFuncAttributeMaxDynamicSharedMemorySize, P2_SMEM);

    init_kernel<<<(Bsz * H + 255) / 256, 256>>>();
    split_x_kernel<<<MTOT * 64 / 256, 256>>>(x);
    split_w_kernel<<<dim3(32, 64, 2), 256>>>(W_fw, W_bw);

    gemm_x_mma<<<dim3(32, 256), 256, G1_SMEM>>>(b_fw, b_bw);

    lstm_persistent<<<128, 256, P2_SMEM>>>(out);
}